// round 6
// baseline (speedup 1.0000x reference)
#include <cuda_runtime.h>

// ---------------- problem constants ----------------
// kv:  (256, 128, 192)   q: (256, 512, 96)
// w_kv:(192,384) b_kv:(384)  w_q:(96,192) b_q:(192)
// w_proj:(192,96) b_proj:(96)
// bias_table:(3375,6)  rel_index:(512,128) int32
// out: (256, 512, 96) fp32

// ---------------- scratch (device globals, allowed) ----------------
__device__ float g_kvp[32768u * 384u];    // kv proj   [B*128, 384]
__device__ float g_qp [131072u * 192u];   // q proj    [B*512, 192] (scaled)
__device__ float g_att[131072u * 192u];   // attn out  [B*512, 192]
__device__ float g_bias[6u * 512u * 128u];// expanded bias [h][q][k]

// ---------------- packed f32x2 helpers (FFMA2 path, sm_103a) ----------------
__device__ __forceinline__ unsigned long long pk2(float x, float y) {
    unsigned long long r;
    asm("mov.b64 %0, {%1, %2};" : "=l"(r) : "f"(x), "f"(y));
    return r;
}
__device__ __forceinline__ void unpk2(unsigned long long v, float& x, float& y) {
    asm("mov.b64 {%0, %1}, %2;" : "=f"(x), "=f"(y) : "l"(v));
}
__device__ __forceinline__ unsigned long long ffma2u(
    unsigned long long a, unsigned long long b, unsigned long long c) {
    unsigned long long d;
    asm("fma.rn.f32x2 %0, %1, %2, %3;" : "=l"(d) : "l"(a), "l"(b), "l"(c));
    return d;
}

// ---------------- bias expansion ----------------
__global__ __launch_bounds__(256) void bias_expand_kernel(
    const float* __restrict__ table, const int* __restrict__ rel)
{
    int idx = blockIdx.x * 256 + threadIdx.x;       // 6*512*128 = 393216
    if (idx >= 6 * 512 * 128) return;
    int h  = idx >> 16;
    int qk = idx & 65535;
    g_bias[idx] = table[rel[qk] * 6 + h];
}

// ---------------- generic GEMM: C = (A @ W + bias) * scale ----------------
// tile 128x128, k-tile 16, 256 threads, 8x8 micro-tile, FFMA2 accumulators.
__global__ __launch_bounds__(256) void gemm_bias_kernel(
    const float* __restrict__ A, const float* __restrict__ W,
    const float* __restrict__ bias, float* __restrict__ C,
    int M, int K, int N, float scale)
{
    __shared__ __align__(16) float As[16][132];   // As[k][m]
    __shared__ __align__(16) float Bs[16][132];   // Bs[k][n]

    const int tid = threadIdx.x;
    const int bm = blockIdx.y * 128;
    const int bn = blockIdx.x * 128;
    const int tx = tid & 15;
    const int ty = tid >> 4;

    unsigned long long acc2[8][4];   // [row][col-pair], each = 2 fp32
#pragma unroll
    for (int i = 0; i < 8; i++)
#pragma unroll
        for (int j = 0; j < 4; j++) acc2[i][j] = 0ull;

    for (int k0 = 0; k0 < K; k0 += 16) {
#pragma unroll
        for (int i = 0; i < 2; i++) {
            int lin = tid + i * 256;
            int row = lin >> 2;
            int kc  = (lin & 3) << 2;
            const float4 va = *(const float4*)(A + (size_t)(bm + row) * K + (k0 + kc));
            As[kc + 0][row] = va.x;
            As[kc + 1][row] = va.y;
            As[kc + 2][row] = va.z;
            As[kc + 3][row] = va.w;
        }
#pragma unroll
        for (int i = 0; i < 2; i++) {
            int lin = tid + i * 256;
            int kk = lin >> 5;
            int nc = (lin & 31) << 2;
            float4 vb;
            if (bn + nc < N)
                vb = *(const float4*)(W + (size_t)(k0 + kk) * N + (bn + nc));
            else
                vb = make_float4(0.f, 0.f, 0.f, 0.f);
            *(float4*)&Bs[kk][nc] = vb;
        }
        __syncthreads();

#pragma unroll
        for (int k = 0; k < 16; k++) {
            float a[8];
            *(float4*)&a[0] = *(const float4*)&As[k][ty * 8];
            *(float4*)&a[4] = *(const float4*)&As[k][ty * 8 + 4];
            ulonglong2 bl = *(const ulonglong2*)&Bs[k][tx * 8];      // pairs (0,1),(2,3)
            ulonglong2 bh = *(const ulonglong2*)&Bs[k][tx * 8 + 4];  // pairs (4,5),(6,7)
#pragma unroll
            for (int i = 0; i < 8; i++) {
                unsigned long long ad = pk2(a[i], a[i]);
                acc2[i][0] = ffma2u(ad, bl.x, acc2[i][0]);
                acc2[i][1] = ffma2u(ad, bl.y, acc2[i][1]);
                acc2[i][2] = ffma2u(ad, bh.x, acc2[i][2]);
                acc2[i][3] = ffma2u(ad, bh.y, acc2[i][3]);
            }
        }
        __syncthreads();
    }

#pragma unroll
    for (int i = 0; i < 8; i++) {
        int row = bm + ty * 8 + i;
#pragma unroll
        for (int j = 0; j < 2; j++) {          // two float4 stores
            int col = bn + tx * 8 + j * 4;
            if (col < N) {
                float x0, x1, x2, x3;
                unpk2(acc2[i][j * 2 + 0], x0, x1);
                unpk2(acc2[i][j * 2 + 1], x2, x3);
                float4 r;
                r.x = (x0 + bias[col + 0]) * scale;
                r.y = (x1 + bias[col + 1]) * scale;
                r.z = (x2 + bias[col + 2]) * scale;
                r.w = (x3 + bias[col + 3]) * scale;
                *(float4*)(C + (size_t)row * N + col) = r;
            }
        }
    }
}

// ---------------- fused attention per (b, h) ----------------
// Block = one (batch, head). 8 warps, each owns 64 q-rows, 8 rows per iter.
// Lane owns 4 consecutive keys in QK^T (swizzled K rows -> LDS.128), Q staged
// in per-warp smem (broadcast reads, no shuffles in QK). AV: lane owns
// (row-group, d-chunk), broadcast P/V loads. All dot products in FFMA2.
// smem = Kt 16K + Vt 16K + scratch 16K = 48 KB static.
__global__ __launch_bounds__(256) void attn_kernel(
    const float* __restrict__ kvp,    // [B*128, 384]
    const float* __restrict__ qp,     // [B*512, 192]  (pre-scaled)
    float* __restrict__ outp)         // [B*512, 192]
{
    __shared__ __align__(16) float Kt[32 * 128];  // Kt[d][ n ^ (4*(d&7)) ]
    __shared__ __align__(16) float Vt[128 * 32];  // Vt[k][ chunk (d4 ^ (k&7)) *4 ]
    __shared__ __align__(16) float Sw[8 * 512];   // per-warp: Q[8][32] then P[4][128]

    const int tid  = threadIdx.x;
    const int w    = tid >> 5;
    const int lane = tid & 31;
    const int b = blockIdx.x / 6;
    const int h = blockIdx.x % 6;

    // ---- load K (d-major, elem-swizzled) and V (k-major, chunk-swizzled) ----
#pragma unroll
    for (int i = 0; i < 4; i++) {
        int lin = tid + 256 * i;          // 0..1023
        int n   = lin & 127;
        int d4  = lin >> 7;               // 0..7
        const float* src = kvp + (size_t)(b * 128 + n) * 384 + h * 32 + d4 * 4;
        float4 kq = *(const float4*)src;
        float4 vq = *(const float4*)(src + 192);
        int c = 16 * (d4 & 1);
        Kt[(4 * d4 + 0) * 128 + (n ^ (c + 0 ))] = kq.x;
        Kt[(4 * d4 + 1) * 128 + (n ^ (c + 4 ))] = kq.y;
        Kt[(4 * d4 + 2) * 128 + (n ^ (c + 8 ))] = kq.z;
        Kt[(4 * d4 + 3) * 128 + (n ^ (c + 12))] = kq.w;
        *(float4*)&Vt[n * 32 + ((d4 ^ (n & 7)) << 2)] = vq;
    }
    __syncthreads();

    const float* qb = qp + (size_t)(b * 512) * 192 + h * 32;
    const float* bb = g_bias + (size_t)h * 65536;
    float*       ob = outp + (size_t)(b * 512) * 192 + h * 32;
    float*       Qw = Sw + w * 512;       // warp-private scratch (Q then P)

    for (int it = 0; it < 8; it++) {
        const int r0 = (w << 6) + (it << 3);

        // ---- stage Q[8][32] into warp scratch ----
        {
            int row = lane >> 3, dq = (lane & 7) << 2;
            float4 q0 = *(const float4*)(qb + (size_t)(r0 + row)     * 192 + dq);
            float4 q1 = *(const float4*)(qb + (size_t)(r0 + 4 + row) * 192 + dq);
            *(float4*)&Qw[row * 32 + dq]       = q0;
            *(float4*)&Qw[(4 + row) * 32 + dq] = q1;
        }
        __syncwarp();

        // ---- QK^T: lane owns keys 4*lane..4*lane+3; acc2[qi][p] = key pairs ----
        unsigned long long acc2[8][2];
#pragma unroll
        for (int qi = 0; qi < 8; qi++) { acc2[qi][0] = 0ull; acc2[qi][1] = 0ull; }

#pragma unroll 2
        for (int dg = 0; dg < 8; dg++) {
            ulonglong2 kk[4];
#pragma unroll
            for (int j = 0; j < 4; j++) {
                int d = 4 * dg + j;
                kk[j] = *(const ulonglong2*)&Kt[d * 128 + 4 * (lane ^ (d & 7))];
            }
#pragma unroll
            for (int qi = 0; qi < 8; qi++) {
                float4 q4 = *(const float4*)&Qw[qi * 32 + dg * 4];  // broadcast
                unsigned long long a0 = pk2(q4.x, q4.x);
                acc2[qi][0] = ffma2u(a0, kk[0].x, acc2[qi][0]);
                acc2[qi][1] = ffma2u(a0, kk[0].y, acc2[qi][1]);
                unsigned long long a1 = pk2(q4.y, q4.y);
                acc2[qi][0] = ffma2u(a1, kk[1].x, acc2[qi][0]);
                acc2[qi][1] = ffma2u(a1, kk[1].y, acc2[qi][1]);
                unsigned long long a2 = pk2(q4.z, q4.z);
                acc2[qi][0] = ffma2u(a2, kk[2].x, acc2[qi][0]);
                acc2[qi][1] = ffma2u(a2, kk[2].y, acc2[qi][1]);
                unsigned long long a3 = pk2(q4.w, q4.w);
                acc2[qi][0] = ffma2u(a3, kk[3].x, acc2[qi][0]);
                acc2[qi][1] = ffma2u(a3, kk[3].y, acc2[qi][1]);
            }
        }
        __syncwarp();   // done reading Qw; P will overwrite it

        // ---- softmax + AV in two 4-row halves (P reuses Qw scratch) ----
#pragma unroll
        for (int h2 = 0; h2 < 2; h2++) {
#pragma unroll
            for (int qi = 0; qi < 4; qi++) {
                int qg = 4 * h2 + qi;
                float4 b4 = *(const float4*)(bb + (size_t)(r0 + qg) * 128 + 4 * lane);
                float s0, s1, s2, s3;
                unpk2(acc2[qg][0], s0, s1);
                unpk2(acc2[qg][1], s2, s3);
                s0 += b4.x; s1 += b4.y; s2 += b4.z; s3 += b4.w;
                float m = fmaxf(fmaxf(s0, s1), fmaxf(s2, s3));
#pragma unroll
                for (int o = 16; o > 0; o >>= 1)
                    m = fmaxf(m, __shfl_xor_sync(0xffffffffu, m, o));
                float e0 = __expf(s0 - m);
                float e1 = __expf(s1 - m);
                float e2 = __expf(s2 - m);
                float e3 = __expf(s3 - m);
                float sum = e0 + e1 + e2 + e3;
#pragma unroll
                for (int o = 16; o > 0; o >>= 1)
                    sum += __shfl_xor_sync(0xffffffffu, sum, o);
                float inv = 1.0f / sum;
                float4 pr = make_float4(e0 * inv, e1 * inv, e2 * inv, e3 * inv);
                *(float4*)&Qw[qi * 128 + 4 * lane] = pr;   // P[qi][4l..4l+3]
            }
            __syncwarp();

            // AV: lane -> (row rg = lane>>3, d-chunk c8 = lane&7)
            const int rg = lane >> 3;
            const int c8 = lane & 7;
            unsigned long long o0 = 0ull, o1 = 0ull;
#pragma unroll 4
            for (int kc = 0; kc < 32; kc++) {
                float4 p4 = *(const float4*)&Qw[rg * 128 + 4 * kc];  // bcast per rg
                int kb = 4 * kc;
                int cb = c8 ^ (4 * (kc & 1));
#pragma unroll
                for (int i = 0; i < 4; i++) {
                    ulonglong2 v2 = *(const ulonglong2*)&Vt[(kb + i) * 32 + 4 * (cb ^ i)];
                    float pe = (i == 0) ? p4.x : (i == 1) ? p4.y : (i == 2) ? p4.z : p4.w;
                    unsigned long long pp = pk2(pe, pe);
                    o0 = ffma2u(pp, v2.x, o0);
                    o1 = ffma2u(pp, v2.y, o1);
                }
            }
            float ox, oy, oz, ow;
            unpk2(o0, ox, oy);
            unpk2(o1, oz, ow);
            *(float4*)(ob + (size_t)(r0 + 4 * h2 + rg) * 192 + 4 * c8) =
                make_float4(ox, oy, oz, ow);
            __syncwarp();   // before next half's P overwrite
        }
    }
}

// ---------------- launch ----------------
extern "C" void kernel_launch(void* const* d_in, const int* in_sizes, int n_in,
                              void* d_out, int out_size)
{
    const float* kv         = (const float*)d_in[0];
    const float* q          = (const float*)d_in[1];
    const float* w_kv       = (const float*)d_in[2];
    const float* b_kv       = (const float*)d_in[3];
    const float* w_q        = (const float*)d_in[4];
    const float* b_q        = (const float*)d_in[5];
    const float* w_proj     = (const float*)d_in[6];
    const float* b_proj     = (const float*)d_in[7];
    const float* bias_table = (const float*)d_in[8];
    const int*   rel_index  = (const int*)  d_in[9];
    float* out = (float*)d_out;

    float *p_kvp, *p_qp, *p_att;
    cudaGetSymbolAddress((void**)&p_kvp, g_kvp);
    cudaGetSymbolAddress((void**)&p_qp,  g_qp);
    cudaGetSymbolAddress((void**)&p_att, g_att);

    const float qscale = 0.17677669529663687f;  // 1/sqrt(32)

    bias_expand_kernel<<<1536, 256>>>(bias_table, rel_index);

    // kv projection: (32768 x 192) @ (192 x 384) + b_kv
    gemm_bias_kernel<<<dim3(3, 256), 256>>>(kv, w_kv, b_kv, p_kvp,
                                            32768, 192, 384, 1.0f);
    // q projection (scaled): (131072 x 96) @ (96 x 192) + b_q
    gemm_bias_kernel<<<dim3(2, 1024), 256>>>(q, w_q, b_q, p_qp,
                                             131072, 96, 192, qscale);
    // fused attention per (batch, head)
    attn_kernel<<<256 * 6, 256>>>(p_kvp, p_qp, p_att);

    // output projection: (131072 x 192) @ (192 x 96) + b_proj
    gemm_bias_kernel<<<dim3(1, 1024), 256>>>(p_att, w_proj, b_proj, out,
                                             131072, 192, 96, 1.0f);
}

// round 7
// speedup vs baseline: 1.0270x; 1.0270x over previous
#include <cuda_runtime.h>

// ---------------- problem constants ----------------
// kv:  (256, 128, 192)   q: (256, 512, 96)
// w_kv:(192,384) b_kv:(384)  w_q:(96,192) b_q:(192)
// w_proj:(192,96) b_proj:(96)
// bias_table:(3375,6)  rel_index:(512,128) int32
// out: (256, 512, 96) fp32

// ---------------- scratch (device globals, allowed) ----------------
__device__ float g_kvp[32768u * 384u];    // kv proj   [B*128, 384]
__device__ float g_qp [131072u * 192u];   // q proj    [B*512, 192] (scaled)
__device__ float g_att[131072u * 192u];   // attn out  [B*512, 192]
__device__ float g_bias[6u * 512u * 128u];// expanded bias [h][q][k]

// ---------------- packed f32x2 helpers (FFMA2 path, sm_103a) ----------------
__device__ __forceinline__ unsigned long long pk2(float x, float y) {
    unsigned long long r;
    asm("mov.b64 %0, {%1, %2};" : "=l"(r) : "f"(x), "f"(y));
    return r;
}
__device__ __forceinline__ void unpk2(unsigned long long v, float& x, float& y) {
    asm("mov.b64 {%0, %1}, %2;" : "=f"(x), "=f"(y) : "l"(v));
}
__device__ __forceinline__ unsigned long long ffma2u(
    unsigned long long a, unsigned long long b, unsigned long long c) {
    unsigned long long d;
    asm("fma.rn.f32x2 %0, %1, %2, %3;" : "=l"(d) : "l"(a), "l"(b), "l"(c));
    return d;
}

// ---------------- bias expansion ----------------
__global__ __launch_bounds__(256) void bias_expand_kernel(
    const float* __restrict__ table, const int* __restrict__ rel)
{
    int idx = blockIdx.x * 256 + threadIdx.x;       // 6*512*128 = 393216
    if (idx >= 6 * 512 * 128) return;
    int h  = idx >> 16;
    int qk = idx & 65535;
    g_bias[idx] = table[rel[qk] * 6 + h];
}

// ---------------- generic GEMM: C = (A @ W + bias) * scale ----------------
// tile 128x128, k-tile 16, 256 threads, 8x8 micro-tile, FFMA2 accumulators.
__global__ __launch_bounds__(256) void gemm_bias_kernel(
    const float* __restrict__ A, const float* __restrict__ W,
    const float* __restrict__ bias, float* __restrict__ C,
    int M, int K, int N, float scale)
{
    __shared__ __align__(16) float As[16][132];   // As[k][m]
    __shared__ __align__(16) float Bs[16][132];   // Bs[k][n]

    const int tid = threadIdx.x;
    const int bm = blockIdx.y * 128;
    const int bn = blockIdx.x * 128;
    const int tx = tid & 15;
    const int ty = tid >> 4;

    unsigned long long acc2[8][4];   // [row][col-pair], each = 2 fp32
#pragma unroll
    for (int i = 0; i < 8; i++)
#pragma unroll
        for (int j = 0; j < 4; j++) acc2[i][j] = 0ull;

    for (int k0 = 0; k0 < K; k0 += 16) {
#pragma unroll
        for (int i = 0; i < 2; i++) {
            int lin = tid + i * 256;
            int row = lin >> 2;
            int kc  = (lin & 3) << 2;
            const float4 va = *(const float4*)(A + (size_t)(bm + row) * K + (k0 + kc));
            As[kc + 0][row] = va.x;
            As[kc + 1][row] = va.y;
            As[kc + 2][row] = va.z;
            As[kc + 3][row] = va.w;
        }
#pragma unroll
        for (int i = 0; i < 2; i++) {
            int lin = tid + i * 256;
            int kk = lin >> 5;
            int nc = (lin & 31) << 2;
            float4 vb;
            if (bn + nc < N)
                vb = *(const float4*)(W + (size_t)(k0 + kk) * N + (bn + nc));
            else
                vb = make_float4(0.f, 0.f, 0.f, 0.f);
            *(float4*)&Bs[kk][nc] = vb;
        }
        __syncthreads();

#pragma unroll
        for (int k = 0; k < 16; k++) {
            float a[8];
            *(float4*)&a[0] = *(const float4*)&As[k][ty * 8];
            *(float4*)&a[4] = *(const float4*)&As[k][ty * 8 + 4];
            ulonglong2 bl = *(const ulonglong2*)&Bs[k][tx * 8];      // pairs (0,1),(2,3)
            ulonglong2 bh = *(const ulonglong2*)&Bs[k][tx * 8 + 4];  // pairs (4,5),(6,7)
#pragma unroll
            for (int i = 0; i < 8; i++) {
                unsigned long long ad = pk2(a[i], a[i]);
                acc2[i][0] = ffma2u(ad, bl.x, acc2[i][0]);
                acc2[i][1] = ffma2u(ad, bl.y, acc2[i][1]);
                acc2[i][2] = ffma2u(ad, bh.x, acc2[i][2]);
                acc2[i][3] = ffma2u(ad, bh.y, acc2[i][3]);
            }
        }
        __syncthreads();
    }

#pragma unroll
    for (int i = 0; i < 8; i++) {
        int row = bm + ty * 8 + i;
#pragma unroll
        for (int j = 0; j < 2; j++) {          // two float4 stores
            int col = bn + tx * 8 + j * 4;
            if (col < N) {
                float x0, x1, x2, x3;
                unpk2(acc2[i][j * 2 + 0], x0, x1);
                unpk2(acc2[i][j * 2 + 1], x2, x3);
                float4 r;
                r.x = (x0 + bias[col + 0]) * scale;
                r.y = (x1 + bias[col + 1]) * scale;
                r.z = (x2 + bias[col + 2]) * scale;
                r.w = (x3 + bias[col + 3]) * scale;
                *(float4*)(C + (size_t)row * N + col) = r;
            }
        }
    }
}

// ---------------- fused attention per (b, h) ----------------
// Block = one (batch, head). 8 warps, each owns 64 q-rows, 8 rows per iter.
// Lane owns 4 consecutive keys in QK^T (swizzled K rows -> LDS.128), Q staged
// in per-warp smem (broadcast reads, no shuffles in QK). AV: lane owns
// (row-group, d-chunk), broadcast P/V loads. All dot products in FFMA2.
// smem = Kt 16K + Vt 16K + scratch 16K = 48 KB static.
// __launch_bounds__(256, 3): cap regs at 85 so 3 CTAs/SM fit (R5 had 88 regs
// -> 2 CTAs -> issue-starved at 34%).
__global__ __launch_bounds__(256, 3) void attn_kernel(
    const float* __restrict__ kvp,    // [B*128, 384]
    const float* __restrict__ qp,     // [B*512, 192]  (pre-scaled)
    float* __restrict__ outp)         // [B*512, 192]
{
    __shared__ __align__(16) float Kt[32 * 128];  // Kt[d][ n ^ swz(d) ]
    __shared__ __align__(16) float Vt[128 * 32];  // Vt[k][ chunk (d4 ^ (k&7)) *4 ]
    __shared__ __align__(16) float Sw[8 * 512];   // per-warp: Q[8][32] then P[4][128]

    const int tid  = threadIdx.x;
    const int w    = tid >> 5;
    const int lane = tid & 31;
    const int b = blockIdx.x / 6;
    const int h = blockIdx.x % 6;

    // ---- load K (d-major, elem-swizzled) and V (k-major, chunk-swizzled) ----
#pragma unroll
    for (int i = 0; i < 4; i++) {
        int lin = tid + 256 * i;          // 0..1023
        int n   = lin & 127;
        int d4  = lin >> 7;               // 0..7
        const float* src = kvp + (size_t)(b * 128 + n) * 384 + h * 32 + d4 * 4;
        float4 kq = *(const float4*)src;
        float4 vq = *(const float4*)(src + 192);
        int c = 16 * (d4 & 1);
        Kt[(4 * d4 + 0) * 128 + (n ^ (c + 0 ))] = kq.x;
        Kt[(4 * d4 + 1) * 128 + (n ^ (c + 4 ))] = kq.y;
        Kt[(4 * d4 + 2) * 128 + (n ^ (c + 8 ))] = kq.z;
        Kt[(4 * d4 + 3) * 128 + (n ^ (c + 12))] = kq.w;
        *(float4*)&Vt[n * 32 + ((d4 ^ (n & 7)) << 2)] = vq;
    }
    __syncthreads();

    const float* qb = qp + (size_t)(b * 512) * 192 + h * 32;
    const float* bb = g_bias + (size_t)h * 65536;
    float*       ob = outp + (size_t)(b * 512) * 192 + h * 32;
    float*       Qw = Sw + w * 512;       // warp-private scratch (Q then P)

    for (int it = 0; it < 8; it++) {
        const int r0 = (w << 6) + (it << 3);

        // ---- stage Q[8][32] into warp scratch ----
        {
            int row = lane >> 3, dq = (lane & 7) << 2;
            float4 q0 = *(const float4*)(qb + (size_t)(r0 + row)     * 192 + dq);
            float4 q1 = *(const float4*)(qb + (size_t)(r0 + 4 + row) * 192 + dq);
            *(float4*)&Qw[row * 32 + dq]       = q0;
            *(float4*)&Qw[(4 + row) * 32 + dq] = q1;
        }
        __syncwarp();

        // ---- QK^T: lane owns keys 4*lane..4*lane+3; acc2[qi][p] = key pairs ----
        unsigned long long acc2[8][2];
#pragma unroll
        for (int qi = 0; qi < 8; qi++) { acc2[qi][0] = 0ull; acc2[qi][1] = 0ull; }

#pragma unroll 2
        for (int dg = 0; dg < 8; dg++) {
            ulonglong2 kk[4];
#pragma unroll
            for (int j = 0; j < 4; j++) {
                int d = 4 * dg + j;
                kk[j] = *(const ulonglong2*)&Kt[d * 128 + 4 * (lane ^ (d & 7))];
            }
#pragma unroll
            for (int qi = 0; qi < 8; qi++) {
                float4 q4 = *(const float4*)&Qw[qi * 32 + dg * 4];  // broadcast
                unsigned long long a0 = pk2(q4.x, q4.x);
                acc2[qi][0] = ffma2u(a0, kk[0].x, acc2[qi][0]);
                acc2[qi][1] = ffma2u(a0, kk[0].y, acc2[qi][1]);
                unsigned long long a1 = pk2(q4.y, q4.y);
                acc2[qi][0] = ffma2u(a1, kk[1].x, acc2[qi][0]);
                acc2[qi][1] = ffma2u(a1, kk[1].y, acc2[qi][1]);
                unsigned long long a2 = pk2(q4.z, q4.z);
                acc2[qi][0] = ffma2u(a2, kk[2].x, acc2[qi][0]);
                acc2[qi][1] = ffma2u(a2, kk[2].y, acc2[qi][1]);
                unsigned long long a3 = pk2(q4.w, q4.w);
                acc2[qi][0] = ffma2u(a3, kk[3].x, acc2[qi][0]);
                acc2[qi][1] = ffma2u(a3, kk[3].y, acc2[qi][1]);
            }
        }
        __syncwarp();   // done reading Qw; P will overwrite it

        // ---- softmax + AV in two 4-row halves (P reuses Qw scratch) ----
#pragma unroll
        for (int h2 = 0; h2 < 2; h2++) {
#pragma unroll
            for (int qi = 0; qi < 4; qi++) {
                int qg = 4 * h2 + qi;
                float4 b4 = *(const float4*)(bb + (size_t)(r0 + qg) * 128 + 4 * lane);
                float s0, s1, s2, s3;
                unpk2(acc2[qg][0], s0, s1);
                unpk2(acc2[qg][1], s2, s3);
                s0 += b4.x; s1 += b4.y; s2 += b4.z; s3 += b4.w;
                float m = fmaxf(fmaxf(s0, s1), fmaxf(s2, s3));
#pragma unroll
                for (int o = 16; o > 0; o >>= 1)
                    m = fmaxf(m, __shfl_xor_sync(0xffffffffu, m, o));
                float e0 = __expf(s0 - m);
                float e1 = __expf(s1 - m);
                float e2 = __expf(s2 - m);
                float e3 = __expf(s3 - m);
                float sum = e0 + e1 + e2 + e3;
#pragma unroll
                for (int o = 16; o > 0; o >>= 1)
                    sum += __shfl_xor_sync(0xffffffffu, sum, o);
                float inv = 1.0f / sum;
                float4 pr = make_float4(e0 * inv, e1 * inv, e2 * inv, e3 * inv);
                *(float4*)&Qw[qi * 128 + 4 * lane] = pr;   // P[qi][4l..4l+3]
            }
            __syncwarp();

            // AV: lane -> (row rg = lane>>3, d-chunk c8 = lane&7)
            const int rg = lane >> 3;
            const int c8 = lane & 7;
            unsigned long long o0 = 0ull, o1 = 0ull;
#pragma unroll 4
            for (int kc = 0; kc < 32; kc++) {
                float4 p4 = *(const float4*)&Qw[rg * 128 + 4 * kc];  // bcast per rg
                int kb = 4 * kc;
                int cb = c8 ^ (4 * (kc & 1));
#pragma unroll
                for (int i = 0; i < 4; i++) {
                    ulonglong2 v2 = *(const ulonglong2*)&Vt[(kb + i) * 32 + 4 * (cb ^ i)];
                    float pe = (i == 0) ? p4.x : (i == 1) ? p4.y : (i == 2) ? p4.z : p4.w;
                    unsigned long long pp = pk2(pe, pe);
                    o0 = ffma2u(pp, v2.x, o0);
                    o1 = ffma2u(pp, v2.y, o1);
                }
            }
            float ox, oy, oz, ow;
            unpk2(o0, ox, oy);
            unpk2(o1, oz, ow);
            *(float4*)(ob + (size_t)(r0 + 4 * h2 + rg) * 192 + 4 * c8) =
                make_float4(ox, oy, oz, ow);
            __syncwarp();   // before next half's P overwrite
        }
    }
}

// ---------------- launch ----------------
extern "C" void kernel_launch(void* const* d_in, const int* in_sizes, int n_in,
                              void* d_out, int out_size)
{
    const float* kv         = (const float*)d_in[0];
    const float* q          = (const float*)d_in[1];
    const float* w_kv       = (const float*)d_in[2];
    const float* b_kv       = (const float*)d_in[3];
    const float* w_q        = (const float*)d_in[4];
    const float* b_q        = (const float*)d_in[5];
    const float* w_proj     = (const float*)d_in[6];
    const float* b_proj     = (const float*)d_in[7];
    const float* bias_table = (const float*)d_in[8];
    const int*   rel_index  = (const int*)  d_in[9];
    float* out = (float*)d_out;

    float *p_kvp, *p_qp, *p_att;
    cudaGetSymbolAddress((void**)&p_kvp, g_kvp);
    cudaGetSymbolAddress((void**)&p_qp,  g_qp);
    cudaGetSymbolAddress((void**)&p_att, g_att);

    const float qscale = 0.17677669529663687f;  // 1/sqrt(32)

    bias_expand_kernel<<<1536, 256>>>(bias_table, rel_index);

    // kv projection: (32768 x 192) @ (192 x 384) + b_kv
    gemm_bias_kernel<<<dim3(3, 256), 256>>>(kv, w_kv, b_kv, p_kvp,
                                            32768, 192, 384, 1.0f);
    // q projection (scaled): (131072 x 96) @ (96 x 192) + b_q
    gemm_bias_kernel<<<dim3(2, 1024), 256>>>(q, w_q, b_q, p_qp,
                                             131072, 96, 192, qscale);
    // fused attention per (batch, head)
    attn_kernel<<<256 * 6, 256>>>(p_kvp, p_qp, p_att);

    // output projection: (131072 x 192) @ (192 x 96) + b_proj
    gemm_bias_kernel<<<dim3(1, 1024), 256>>>(p_att, w_proj, b_proj, out,
                                             131072, 192, 96, 1.0f);
}

// round 12
// speedup vs baseline: 1.6117x; 1.5693x over previous
#include <cuda_runtime.h>
#include <cuda_bf16.h>
#include <cstdint>

// ---------------- problem constants ----------------
// kv:  (256, 128, 192)   q: (256, 512, 96)
// w_kv:(192,384) b_kv:(384)  w_q:(96,192) b_q:(192)
// w_proj:(192,96) b_proj:(96)
// bias_table:(3375,6)  rel_index:(512,128) int32
// out: (256, 512, 96) fp32

// ---------------- scratch (device globals, allowed) ----------------
__device__ float g_kvp[32768u * 384u];    // kv proj   [B*128, 384]
__device__ float g_qp [131072u * 192u];   // q proj    [B*512, 192] (scaled)
__device__ float g_att[131072u * 192u];   // attn out  [B*512, 192]
__device__ float g_bias[6u * 512u * 128u];// expanded bias [h][q][k]

// ---------------- packed f32x2 helpers (FFMA2 path, sm_103a) ----------------
__device__ __forceinline__ unsigned long long pk2(float x, float y) {
    unsigned long long r;
    asm("mov.b64 %0, {%1, %2};" : "=l"(r) : "f"(x), "f"(y));
    return r;
}
__device__ __forceinline__ void unpk2(unsigned long long v, float& x, float& y) {
    asm("mov.b64 {%0, %1}, %2;" : "=f"(x), "=f"(y) : "l"(v));
}
__device__ __forceinline__ unsigned long long ffma2u(
    unsigned long long a, unsigned long long b, unsigned long long c) {
    unsigned long long d;
    asm("fma.rn.f32x2 %0, %1, %2, %3;" : "=l"(d) : "l"(a), "l"(b), "l"(c));
    return d;
}

// ---------------- warp-MMA helpers (baseline ISA: sm_80+) ----------------
__device__ __forceinline__ uint32_t smem_u32(const void* p) {
    uint32_t a;
    asm("{ .reg .u64 t; cvta.to.shared.u64 t, %1; cvt.u32.u64 %0, t; }"
        : "=r"(a) : "l"(p));
    return a;
}
__device__ __forceinline__ void ldsm4(uint32_t* r, uint32_t addr) {
    asm volatile("ldmatrix.sync.aligned.m8n8.x4.shared.b16 {%0,%1,%2,%3}, [%4];"
        : "=r"(r[0]), "=r"(r[1]), "=r"(r[2]), "=r"(r[3]) : "r"(addr));
}
__device__ __forceinline__ void ldsm4t(uint32_t* r, uint32_t addr) {
    asm volatile("ldmatrix.sync.aligned.m8n8.x4.trans.shared.b16 {%0,%1,%2,%3}, [%4];"
        : "=r"(r[0]), "=r"(r[1]), "=r"(r[2]), "=r"(r[3]) : "r"(addr));
}
// D(f32) += A(bf16) * B(bf16), m16n8k16, A row-major, B col-major
__device__ __forceinline__ void mma16816(float* c, const uint32_t* a,
                                         uint32_t b0, uint32_t b1) {
    asm volatile(
        "mma.sync.aligned.m16n8k16.row.col.f32.bf16.bf16.f32 "
        "{%0,%1,%2,%3}, {%4,%5,%6,%7}, {%8,%9}, {%0,%1,%2,%3};"
        : "+f"(c[0]), "+f"(c[1]), "+f"(c[2]), "+f"(c[3])
        : "r"(a[0]), "r"(a[1]), "r"(a[2]), "r"(a[3]), "r"(b0), "r"(b1));
}
// split (x,y) into bf16 hi pair (truncation) + bf16 lo pair (rn of remainder)
// pair packing: low 16 bits = x, high 16 bits = y (k-ascending order).
__device__ __forceinline__ void split_pair(float x, float y,
                                           uint32_t& hi, uint32_t& lo) {
    uint32_t bx = __float_as_uint(x);
    uint32_t by = __float_as_uint(y);
    uint32_t hpk;
    asm("prmt.b32 %0, %1, %2, 0x7632;" : "=r"(hpk) : "r"(bx), "r"(by));
    float lx = x - __uint_as_float(bx & 0xFFFF0000u);
    float ly = y - __uint_as_float(by & 0xFFFF0000u);
    uint32_t lpk;
    asm("cvt.rn.bf16x2.f32 %0, %1, %2;" : "=r"(lpk) : "f"(ly), "f"(lx));
    hi = hpk; lo = lpk;
}

// ---------------- bias expansion ----------------
__global__ __launch_bounds__(256) void bias_expand_kernel(
    const float* __restrict__ table, const int* __restrict__ rel)
{
    int idx = blockIdx.x * 256 + threadIdx.x;       // 6*512*128 = 393216
    if (idx >= 6 * 512 * 128) return;
    int h  = idx >> 16;
    int qk = idx & 65535;
    g_bias[idx] = table[rel[qk] * 6 + h];
}

// ---------------- generic GEMM: C = (A @ W + bias) * scale (FFMA2) ----------------
__global__ __launch_bounds__(256) void gemm_bias_kernel(
    const float* __restrict__ A, const float* __restrict__ W,
    const float* __restrict__ bias, float* __restrict__ C,
    int M, int K, int N, float scale)
{
    __shared__ __align__(16) float As[16][132];   // As[k][m]
    __shared__ __align__(16) float Bs[16][132];   // Bs[k][n]

    const int tid = threadIdx.x;
    const int bm = blockIdx.y * 128;
    const int bn = blockIdx.x * 128;
    const int tx = tid & 15;
    const int ty = tid >> 4;

    unsigned long long acc2[8][4];
#pragma unroll
    for (int i = 0; i < 8; i++)
#pragma unroll
        for (int j = 0; j < 4; j++) acc2[i][j] = 0ull;

    for (int k0 = 0; k0 < K; k0 += 16) {
#pragma unroll
        for (int i = 0; i < 2; i++) {
            int lin = tid + i * 256;
            int row = lin >> 2;
            int kc  = (lin & 3) << 2;
            const float4 va = *(const float4*)(A + (size_t)(bm + row) * K + (k0 + kc));
            As[kc + 0][row] = va.x;
            As[kc + 1][row] = va.y;
            As[kc + 2][row] = va.z;
            As[kc + 3][row] = va.w;
        }
#pragma unroll
        for (int i = 0; i < 2; i++) {
            int lin = tid + i * 256;
            int kk = lin >> 5;
            int nc = (lin & 31) << 2;
            float4 vb;
            if (bn + nc < N)
                vb = *(const float4*)(W + (size_t)(k0 + kk) * N + (bn + nc));
            else
                vb = make_float4(0.f, 0.f, 0.f, 0.f);
            *(float4*)&Bs[kk][nc] = vb;
        }
        __syncthreads();

#pragma unroll
        for (int k = 0; k < 16; k++) {
            float a[8];
            *(float4*)&a[0] = *(const float4*)&As[k][ty * 8];
            *(float4*)&a[4] = *(const float4*)&As[k][ty * 8 + 4];
            ulonglong2 bl = *(const ulonglong2*)&Bs[k][tx * 8];
            ulonglong2 bh = *(const ulonglong2*)&Bs[k][tx * 8 + 4];
#pragma unroll
            for (int i = 0; i < 8; i++) {
                unsigned long long ad = pk2(a[i], a[i]);
                acc2[i][0] = ffma2u(ad, bl.x, acc2[i][0]);
                acc2[i][1] = ffma2u(ad, bl.y, acc2[i][1]);
                acc2[i][2] = ffma2u(ad, bh.x, acc2[i][2]);
                acc2[i][3] = ffma2u(ad, bh.y, acc2[i][3]);
            }
        }
        __syncthreads();
    }

#pragma unroll
    for (int i = 0; i < 8; i++) {
        int row = bm + ty * 8 + i;
#pragma unroll
        for (int j = 0; j < 2; j++) {
            int col = bn + tx * 8 + j * 4;
            if (col < N) {
                float x0, x1, x2, x3;
                unpk2(acc2[i][j * 2 + 0], x0, x1);
                unpk2(acc2[i][j * 2 + 1], x2, x3);
                float4 r;
                r.x = (x0 + bias[col + 0]) * scale;
                r.y = (x1 + bias[col + 1]) * scale;
                r.z = (x2 + bias[col + 2]) * scale;
                r.w = (x3 + bias[col + 3]) * scale;
                *(float4*)(C + (size_t)row * N + col) = r;
            }
        }
    }
}

// ================= warp-MMA attention (split bf16, HMMA) =================
// One CTA per (b, h); 256 threads = 8 warps. 4 outer q-blocks of 128 rows;
// each warp owns one 16-row strip per block.
// QK^T: S(16x128) via m16n8k16, 3 split terms (qh*kh + qh*kl + ql*kh).
// Softmax in registers (bias from L2-resident g_bias, deferred 1/sum).
// AV: P reused directly as A fragments (C-frag == A-frag layout trick),
// V fragments via ldmatrix.trans, 3 split terms.
//
// SMEM: 6 tiles of 128 rows x 64 B (32 bf16), XOR-swizzled 16B chunks:
//   chunk addr = row*64 + ((c ^ ((row>>1)&3)) << 4)    -> conflict-free ldmatrix
// Khi 0 | Klo 8K | Vhi 16K | Vlo 24K | Qhi 32K | Qlo 40K   = 48 KB static.
#define SWZ(row, c) (((row) << 6) + ((((c) ^ (((row) >> 1) & 3))) << 4))

__global__ __launch_bounds__(256) void attn_mma_kernel(
    const float* __restrict__ kvp,    // [B*128, 384]
    const float* __restrict__ qp,     // [B*512, 192]  (pre-scaled)
    float* __restrict__ outp)         // [B*512, 192]
{
    __shared__ __align__(16) char smem[49152];
    const uint32_t sK_hi = smem_u32(smem);
    const uint32_t sK_lo = sK_hi + 8192;
    const uint32_t sV_hi = sK_hi + 16384;
    const uint32_t sV_lo = sK_hi + 24576;
    const uint32_t sQ_hi = sK_hi + 32768;
    const uint32_t sQ_lo = sK_hi + 40960;

    const int tid  = threadIdx.x;
    const int w    = tid >> 5;
    const int lane = tid & 31;
    const int b = blockIdx.x / 6;
    const int h = blockIdx.x % 6;

    // ---- prologue: K,V -> smem, split bf16. thread = (row tid>>1, d-half tid&1)
    {
        const int r  = tid >> 1;
        const int hf = tid & 1;
        const float* src = kvp + (size_t)(b * 128 + r) * 384 + h * 32 + hf * 16;
        float kb[16], vb[16];
#pragma unroll
        for (int j = 0; j < 4; j++) {
            float4 f = *(const float4*)(src + 4 * j);
            kb[4*j] = f.x; kb[4*j+1] = f.y; kb[4*j+2] = f.z; kb[4*j+3] = f.w;
            float4 g = *(const float4*)(src + 192 + 4 * j);
            vb[4*j] = g.x; vb[4*j+1] = g.y; vb[4*j+2] = g.z; vb[4*j+3] = g.w;
        }
        uint32_t kh[8], kl[8], vh[8], vl[8];
#pragma unroll
        for (int p = 0; p < 8; p++) {
            split_pair(kb[2*p], kb[2*p+1], kh[p], kl[p]);
            split_pair(vb[2*p], vb[2*p+1], vh[p], vl[p]);
        }
#pragma unroll
        for (int j = 0; j < 2; j++) {           // two 16B chunks per half-row
            int off = SWZ(r, hf * 2 + j);
            *(uint4*)(smem + 0     + off) = make_uint4(kh[4*j], kh[4*j+1], kh[4*j+2], kh[4*j+3]);
            *(uint4*)(smem + 8192  + off) = make_uint4(kl[4*j], kl[4*j+1], kl[4*j+2], kl[4*j+3]);
            *(uint4*)(smem + 16384 + off) = make_uint4(vh[4*j], vh[4*j+1], vh[4*j+2], vh[4*j+3]);
            *(uint4*)(smem + 24576 + off) = make_uint4(vl[4*j], vl[4*j+1], vl[4*j+2], vl[4*j+3]);
        }
    }

    for (int it = 0; it < 4; it++) {
        // ---- load Q block (128 rows), split bf16 ----
        {
            const int r  = tid >> 1;
            const int hf = tid & 1;
            const float* src = qp + (size_t)(b * 512 + it * 128 + r) * 192 + h * 32 + hf * 16;
            float qb[16];
#pragma unroll
            for (int j = 0; j < 4; j++) {
                float4 f = *(const float4*)(src + 4 * j);
                qb[4*j] = f.x; qb[4*j+1] = f.y; qb[4*j+2] = f.z; qb[4*j+3] = f.w;
            }
            uint32_t qh[8], ql[8];
#pragma unroll
            for (int p = 0; p < 8; p++)
                split_pair(qb[2*p], qb[2*p+1], qh[p], ql[p]);
#pragma unroll
            for (int j = 0; j < 2; j++) {
                int off = SWZ(r, hf * 2 + j);
                *(uint4*)(smem + 32768 + off) = make_uint4(qh[4*j], qh[4*j+1], qh[4*j+2], qh[4*j+3]);
                *(uint4*)(smem + 40960 + off) = make_uint4(ql[4*j], ql[4*j+1], ql[4*j+2], ql[4*j+3]);
            }
        }
        __syncthreads();

        const int m0 = w * 16;   // strip rows within this q-block

        // ---- Q A-fragments: [hilo][k-step s][4], matrices ordered a0..a3 ----
        uint32_t qa[2][2][4];
        {
            int rr = m0 + ((lane >> 3) & 1) * 8 + (lane & 7);
            int cb = lane >> 4;                    // chunk within k-step
#pragma unroll
            for (int s = 0; s < 2; s++) {
                int off = SWZ(rr, 2 * s + cb);
                ldsm4(qa[0][s], sQ_hi + off);
                ldsm4(qa[1][s], sQ_lo + off);
            }
        }

        // ---- S = Q K^T (16 x 128), 3 split terms ----
        float sacc[16][4];
#pragma unroll
        for (int n = 0; n < 16; n++)
#pragma unroll
            for (int e = 0; e < 4; e++) sacc[n][e] = 0.f;

#pragma unroll
        for (int n = 0; n < 16; n++) {
            // K b-frags: matrices = chunks c=0..3 of key rows n*8..n*8+7
            int rr = n * 8 + (lane & 7);
            int off = SWZ(rr, lane >> 3);
            uint32_t kh[4], kl[4];
            ldsm4(kh, sK_hi + off);
            ldsm4(kl, sK_lo + off);
            mma16816(sacc[n], qa[0][0], kh[0], kh[1]);   // qh*kh  (d 0-15)
            mma16816(sacc[n], qa[0][1], kh[2], kh[3]);   //        (d 16-31)
            mma16816(sacc[n], qa[0][0], kl[0], kl[1]);   // qh*kl
            mma16816(sacc[n], qa[0][1], kl[2], kl[3]);
            mma16816(sacc[n], qa[1][0], kh[0], kh[1]);   // ql*kh
            mma16816(sacc[n], qa[1][1], kh[2], kh[3]);
        }

        // ---- bias + softmax (rows r1 = lane>>2, r2 = r1+8; cols 2*(lane&3)+{0,1}+8n)
        const int qg1 = it * 128 + m0 + (lane >> 2);
        const int qg2 = qg1 + 8;
        const float* bp1 = g_bias + (size_t)h * 65536 + (size_t)qg1 * 128 + 2 * (lane & 3);
        const float* bp2 = g_bias + (size_t)h * 65536 + (size_t)qg2 * 128 + 2 * (lane & 3);
        float mx1 = -1e30f, mx2 = -1e30f;
#pragma unroll
        for (int n = 0; n < 16; n++) {
            float2 b1 = *(const float2*)(bp1 + 8 * n);
            float2 b2 = *(const float2*)(bp2 + 8 * n);
            sacc[n][0] += b1.x; sacc[n][1] += b1.y;
            sacc[n][2] += b2.x; sacc[n][3] += b2.y;
            mx1 = fmaxf(mx1, fmaxf(sacc[n][0], sacc[n][1]));
            mx2 = fmaxf(mx2, fmaxf(sacc[n][2], sacc[n][3]));
        }
        mx1 = fmaxf(mx1, __shfl_xor_sync(0xffffffffu, mx1, 1));
        mx1 = fmaxf(mx1, __shfl_xor_sync(0xffffffffu, mx1, 2));
        mx2 = fmaxf(mx2, __shfl_xor_sync(0xffffffffu, mx2, 1));
        mx2 = fmaxf(mx2, __shfl_xor_sync(0xffffffffu, mx2, 2));

        float sum1 = 0.f, sum2 = 0.f;
#pragma unroll
        for (int n = 0; n < 16; n++) {
            sacc[n][0] = __expf(sacc[n][0] - mx1); sum1 += sacc[n][0];
            sacc[n][1] = __expf(sacc[n][1] - mx1); sum1 += sacc[n][1];
            sacc[n][2] = __expf(sacc[n][2] - mx2); sum2 += sacc[n][2];
            sacc[n][3] = __expf(sacc[n][3] - mx2); sum2 += sacc[n][3];
        }
        sum1 += __shfl_xor_sync(0xffffffffu, sum1, 1);
        sum1 += __shfl_xor_sync(0xffffffffu, sum1, 2);
        sum2 += __shfl_xor_sync(0xffffffffu, sum2, 1);
        sum2 += __shfl_xor_sync(0xffffffffu, sum2, 2);
        const float inv1 = 1.0f / sum1;
        const float inv2 = 1.0f / sum2;

        // ---- P (unnormalized) -> A-fragments, split bf16 ----
        // step s keys 16s..16s+15: a0 = frag2s(c0,c1), a1 = frag2s(c2,c3),
        //                          a2 = frag2s+1(c0,c1), a3 = frag2s+1(c2,c3)
        uint32_t pah[8][4], pal[8][4];
#pragma unroll
        for (int s = 0; s < 8; s++) {
            split_pair(sacc[2*s][0],   sacc[2*s][1],   pah[s][0], pal[s][0]);
            split_pair(sacc[2*s][2],   sacc[2*s][3],   pah[s][1], pal[s][1]);
            split_pair(sacc[2*s+1][0], sacc[2*s+1][1], pah[s][2], pal[s][2]);
            split_pair(sacc[2*s+1][2], sacc[2*s+1][3], pah[s][3], pal[s][3]);
        }

        // ---- O = P V (16 x 32), 3 split terms ----
        float oacc[4][4];
#pragma unroll
        for (int n = 0; n < 4; n++)
#pragma unroll
            for (int e = 0; e < 4; e++) oacc[n][e] = 0.f;

#pragma unroll
        for (int n = 0; n < 4; n++) {           // d-groups of 8
#pragma unroll
            for (int sh = 0; sh < 4; sh++) {    // key 32-chunks
                // V b-frags via trans: matrices = key octets, fixed d-chunk n
                int rr = sh * 32 + (lane >> 3) * 8 + (lane & 7);
                int off = SWZ(rr, n);
                uint32_t vh[4], vl[4];
                ldsm4t(vh, sV_hi + off);
                ldsm4t(vl, sV_lo + off);
                int s0 = sh * 2, s1 = s0 + 1;
                mma16816(oacc[n], pah[s0], vh[0], vh[1]);   // Ph*Vh
                mma16816(oacc[n], pah[s1], vh[2], vh[3]);
                mma16816(oacc[n], pal[s0], vh[0], vh[1]);   // Pl*Vh
                mma16816(oacc[n], pal[s1], vh[2], vh[3]);
                mma16816(oacc[n], pah[s0], vl[0], vl[1]);   // Ph*Vl
                mma16816(oacc[n], pah[s1], vl[2], vl[3]);
            }
        }

        // ---- store O (normalize by deferred 1/sum) ----
        float* o1 = outp + (size_t)(b * 512 + qg1) * 192 + h * 32 + 2 * (lane & 3);
        float* o2 = outp + (size_t)(b * 512 + qg2) * 192 + h * 32 + 2 * (lane & 3);
#pragma unroll
        for (int n = 0; n < 4; n++) {
            *(float2*)(o1 + 8 * n) = make_float2(oacc[n][0] * inv1, oacc[n][1] * inv1);
            *(float2*)(o2 + 8 * n) = make_float2(oacc[n][2] * inv2, oacc[n][3] * inv2);
        }
        __syncthreads();   // before next block overwrites Q tiles
    }
}

// ---------------- launch ----------------
extern "C" void kernel_launch(void* const* d_in, const int* in_sizes, int n_in,
                              void* d_out, int out_size)
{
    const float* kv         = (const float*)d_in[0];
    const float* q          = (const float*)d_in[1];
    const float* w_kv       = (const float*)d_in[2];
    const float* b_kv       = (const float*)d_in[3];
    const float* w_q        = (const float*)d_in[4];
    const float* b_q        = (const float*)d_in[5];
    const float* w_proj     = (const float*)d_in[6];
    const float* b_proj     = (const float*)d_in[7];
    const float* bias_table = (const float*)d_in[8];
    const int*   rel_index  = (const int*)  d_in[9];
    float* out = (float*)d_out;

    float *p_kvp, *p_qp, *p_att;
    cudaGetSymbolAddress((void**)&p_kvp, g_kvp);
    cudaGetSymbolAddress((void**)&p_qp,  g_qp);
    cudaGetSymbolAddress((void**)&p_att, g_att);

    const float qscale = 0.17677669529663687f;  // 1/sqrt(32)

    bias_expand_kernel<<<1536, 256>>>(bias_table, rel_index);

    // kv projection: (32768 x 192) @ (192 x 384) + b_kv
    gemm_bias_kernel<<<dim3(3, 256), 256>>>(kv, w_kv, b_kv, p_kvp,
                                            32768, 192, 384, 1.0f);
    // q projection (scaled): (131072 x 96) @ (96 x 192) + b_q
    gemm_bias_kernel<<<dim3(2, 1024), 256>>>(q, w_q, b_q, p_qp,
                                             131072, 96, 192, qscale);
    // warp-MMA fused attention: one CTA per (batch, head)
    attn_mma_kernel<<<256 * 6, 256>>>(p_kvp, p_qp, p_att);

    // output projection: (131072 x 192) @ (192 x 96) + b_proj
    gemm_bias_kernel<<<dim3(1, 1024), 256>>>(p_att, w_proj, b_proj, out,
                                             131072, 192, 96, 1.0f);
}

// round 13
// speedup vs baseline: 1.9690x; 1.2217x over previous
#include <cuda_runtime.h>
#include <cuda_bf16.h>
#include <cstdint>

// ---------------- problem constants ----------------
// kv:  (256, 128, 192)   q: (256, 512, 96)
// w_kv:(192,384) b_kv:(384)  w_q:(96,192) b_q:(192)
// w_proj:(192,96) b_proj:(96)
// bias_table:(3375,6)  rel_index:(512,128) int32
// out: (256, 512, 96) fp32

// ---------------- scratch (device globals, allowed) ----------------
__device__ float g_kvp[32768u * 384u];    // kv proj   [B*128, 384]
__device__ float g_qp [131072u * 192u];   // q proj    [B*512, 192] (scaled)
__device__ float g_att[131072u * 192u];   // attn out  [B*512, 192]
__device__ float g_bias[6u * 512u * 128u];// expanded bias [h][q][k]

// ---------------- warp-MMA helpers (baseline ISA: sm_80+) ----------------
__device__ __forceinline__ uint32_t smem_u32(const void* p) {
    uint32_t a;
    asm("{ .reg .u64 t; cvta.to.shared.u64 t, %1; cvt.u32.u64 %0, t; }"
        : "=r"(a) : "l"(p));
    return a;
}
__device__ __forceinline__ void ldsm4(uint32_t* r, uint32_t addr) {
    asm volatile("ldmatrix.sync.aligned.m8n8.x4.shared.b16 {%0,%1,%2,%3}, [%4];"
        : "=r"(r[0]), "=r"(r[1]), "=r"(r[2]), "=r"(r[3]) : "r"(addr));
}
__device__ __forceinline__ void ldsm4t(uint32_t* r, uint32_t addr) {
    asm volatile("ldmatrix.sync.aligned.m8n8.x4.trans.shared.b16 {%0,%1,%2,%3}, [%4];"
        : "=r"(r[0]), "=r"(r[1]), "=r"(r[2]), "=r"(r[3]) : "r"(addr));
}
// D(f32) += A(bf16) * B(bf16), m16n8k16, A row-major, B col-major
__device__ __forceinline__ void mma16816(float* c, const uint32_t* a,
                                         uint32_t b0, uint32_t b1) {
    asm volatile(
        "mma.sync.aligned.m16n8k16.row.col.f32.bf16.bf16.f32 "
        "{%0,%1,%2,%3}, {%4,%5,%6,%7}, {%8,%9}, {%0,%1,%2,%3};"
        : "+f"(c[0]), "+f"(c[1]), "+f"(c[2]), "+f"(c[3])
        : "r"(a[0]), "r"(a[1]), "r"(a[2]), "r"(a[3]), "r"(b0), "r"(b1));
}
// split (x,y) into bf16 hi pair (truncation) + bf16 lo pair (rn of remainder)
// pair packing: low 16 bits = x, high 16 bits = y (ascending order).
__device__ __forceinline__ void split_pair(float x, float y,
                                           uint32_t& hi, uint32_t& lo) {
    uint32_t bx = __float_as_uint(x);
    uint32_t by = __float_as_uint(y);
    uint32_t hpk;
    asm("prmt.b32 %0, %1, %2, 0x7632;" : "=r"(hpk) : "r"(bx), "r"(by));
    float lx = x - __uint_as_float(bx & 0xFFFF0000u);
    float ly = y - __uint_as_float(by & 0xFFFF0000u);
    uint32_t lpk;
    asm("cvt.rn.bf16x2.f32 %0, %1, %2;" : "=r"(lpk) : "f"(ly), "f"(lx));
    hi = hpk; lo = lpk;
}

// swizzled 16B-chunk offset inside a 64B-row tile (4 chunks/row)
#define SWZ(row, c)  (((row) << 6) + ((((c) ^ (((row) >> 1) & 3))) << 4))
// swizzled 16B-chunk offset inside a 256B-row tile (16 chunks/row)
#define SWZW(row, c) (((row) << 8) + ((((c) ^ ((row) & 7))) << 4))

// ---------------- bias expansion ----------------
__global__ __launch_bounds__(256) void bias_expand_kernel(
    const float* __restrict__ table, const int* __restrict__ rel)
{
    int idx = blockIdx.x * 256 + threadIdx.x;       // 6*512*128 = 393216
    if (idx >= 6 * 512 * 128) return;
    int h  = idx >> 16;
    int qk = idx & 65535;
    g_bias[idx] = table[rel[qk] * 6 + h];
}

// ================= split-bf16 HMMA GEMM =================
// C[M,N] = (A[M,K] @ W[K,N] + bias[N]) * scale, fp32 in/out.
// CTA tile 128M x 128N, K in 32-chunks. 8 warps; warp = 16-row strip x 128 cols.
// 3 split terms: Ah*Wh + Al*Wh + Ah*Wl  (error ~2^-16).
// A tile: 128 rows x 32 bf16 (64B rows, SWZ) -> ldsm4 (non-trans), like attn Q.
// W tile: 32 k-rows x 128 n bf16 (256B rows, SWZW) -> ldsm4t, like attn V.
// smem: Ah 8K | Al 8K | Wh 8K | Wl 8K = 32 KB static.
// Requires: M % 128 == 0, K % 32 == 0. N handled by zero-pad + masked stores.
__global__ __launch_bounds__(256) void gemm_mma_kernel(
    const float* __restrict__ A, const float* __restrict__ W,
    const float* __restrict__ bias, float* __restrict__ C,
    int M, int K, int N, float scale)
{
    __shared__ __align__(16) char smem[32768];
    const uint32_t sA_hi = smem_u32(smem);
    const uint32_t sA_lo = sA_hi + 8192;
    const uint32_t sW_hi = sA_hi + 16384;
    const uint32_t sW_lo = sA_hi + 24576;

    const int tid  = threadIdx.x;
    const int w    = tid >> 5;
    const int lane = tid & 31;
    const int bm = blockIdx.y * 128;
    const int bn = blockIdx.x * 128;

    float acc[16][4];
#pragma unroll
    for (int n = 0; n < 16; n++)
#pragma unroll
        for (int e = 0; e < 4; e++) acc[n][e] = 0.f;

    const int m0 = w * 16;
    // A-frag addressing (same as attention Q): row and chunk-base per lane
    const int arr = m0 + ((lane >> 3) & 1) * 8 + (lane & 7);
    const int acb = lane >> 4;

    for (int k0 = 0; k0 < K; k0 += 32) {
        // ---- load A chunk: thread (row tid>>1, k-half tid&1) ----
        {
            const int r  = tid >> 1;
            const int hf = tid & 1;
            const float* src = A + (size_t)(bm + r) * K + k0 + hf * 16;
            float av[16];
#pragma unroll
            for (int j = 0; j < 4; j++) {
                float4 f = *(const float4*)(src + 4 * j);
                av[4*j] = f.x; av[4*j+1] = f.y; av[4*j+2] = f.z; av[4*j+3] = f.w;
            }
            uint32_t hi[8], lo[8];
#pragma unroll
            for (int p = 0; p < 8; p++)
                split_pair(av[2*p], av[2*p+1], hi[p], lo[p]);
#pragma unroll
            for (int j = 0; j < 2; j++) {
                int off = SWZ(r, hf * 2 + j);
                *(uint4*)(smem + 0    + off) = make_uint4(hi[4*j], hi[4*j+1], hi[4*j+2], hi[4*j+3]);
                *(uint4*)(smem + 8192 + off) = make_uint4(lo[4*j], lo[4*j+1], lo[4*j+2], lo[4*j+3]);
            }
        }
        // ---- load W chunk: 32 k-rows x 128 n; unit = 8 n-values ----
#pragma unroll
        for (int i = 0; i < 2; i++) {
            int lin = tid + 256 * i;          // 0..511
            int kk  = lin >> 4;               // 0..31
            int c   = lin & 15;               // n-octet
            int n0  = bn + 8 * c;
            float wv[8];
            if (n0 + 4 <= N) {
                float4 f = *(const float4*)(W + (size_t)(k0 + kk) * N + n0);
                wv[0]=f.x; wv[1]=f.y; wv[2]=f.z; wv[3]=f.w;
            } else { wv[0]=wv[1]=wv[2]=wv[3]=0.f; }
            if (n0 + 8 <= N) {
                float4 f = *(const float4*)(W + (size_t)(k0 + kk) * N + n0 + 4);
                wv[4]=f.x; wv[5]=f.y; wv[6]=f.z; wv[7]=f.w;
            } else { wv[4]=wv[5]=wv[6]=wv[7]=0.f; }
            uint32_t hi[4], lo[4];
#pragma unroll
            for (int p = 0; p < 4; p++)
                split_pair(wv[2*p], wv[2*p+1], hi[p], lo[p]);
            int off = SWZW(kk, c);
            *(uint4*)(smem + 16384 + off) = make_uint4(hi[0], hi[1], hi[2], hi[3]);
            *(uint4*)(smem + 24576 + off) = make_uint4(lo[0], lo[1], lo[2], lo[3]);
        }
        __syncthreads();

        // ---- A fragments: [hilo][k-step][4] ----
        uint32_t ah[2][4], al[2][4];
#pragma unroll
        for (int s = 0; s < 2; s++) {
            int off = SWZ(arr, 2 * s + acb);
            ldsm4(ah[s], sA_hi + off);
            ldsm4(al[s], sA_lo + off);
        }

        // ---- per n-octet: ldsm4t W (4 k-octets), 6 mma ----
#pragma unroll
        for (int no = 0; no < 16; no++) {
            int off = SWZW(lane, no);         // rows = lane (0..31), chunk no
            uint32_t wh[4], wl[4];
            ldsm4t(wh, sW_hi + off);
            ldsm4t(wl, sW_lo + off);
            mma16816(acc[no], ah[0], wh[0], wh[1]);   // Ah*Wh  k 0-15
            mma16816(acc[no], ah[1], wh[2], wh[3]);   //        k 16-31
            mma16816(acc[no], al[0], wh[0], wh[1]);   // Al*Wh
            mma16816(acc[no], al[1], wh[2], wh[3]);
            mma16816(acc[no], ah[0], wl[0], wl[1]);   // Ah*Wl
            mma16816(acc[no], ah[1], wl[2], wl[3]);
        }
        __syncthreads();
    }

    // ---- epilogue: bias + scale, masked float2 stores ----
    const int r1 = bm + m0 + (lane >> 2);
    const int r2 = r1 + 8;
    const int cb2 = 2 * (lane & 3);
#pragma unroll
    for (int no = 0; no < 16; no++) {
        int col = bn + 8 * no + cb2;
        if (col < N) {
            float2 bv = *(const float2*)(bias + col);
            *(float2*)(C + (size_t)r1 * N + col) =
                make_float2((acc[no][0] + bv.x) * scale, (acc[no][1] + bv.y) * scale);
            *(float2*)(C + (size_t)r2 * N + col) =
                make_float2((acc[no][2] + bv.x) * scale, (acc[no][3] + bv.y) * scale);
        }
    }
}

// ================= warp-MMA attention (split bf16, HMMA) =================
// One CTA per (b, h); 256 threads = 8 warps. 4 outer q-blocks of 128 rows;
// each warp owns one 16-row strip per block.
__global__ __launch_bounds__(256) void attn_mma_kernel(
    const float* __restrict__ kvp,    // [B*128, 384]
    const float* __restrict__ qp,     // [B*512, 192]  (pre-scaled)
    float* __restrict__ outp)         // [B*512, 192]
{
    __shared__ __align__(16) char smem[49152];
    const uint32_t sK_hi = smem_u32(smem);
    const uint32_t sK_lo = sK_hi + 8192;
    const uint32_t sV_hi = sK_hi + 16384;
    const uint32_t sV_lo = sK_hi + 24576;
    const uint32_t sQ_hi = sK_hi + 32768;
    const uint32_t sQ_lo = sK_hi + 40960;

    const int tid  = threadIdx.x;
    const int w    = tid >> 5;
    const int lane = tid & 31;
    const int b = blockIdx.x / 6;
    const int h = blockIdx.x % 6;

    // ---- prologue: K,V -> smem, split bf16. thread = (row tid>>1, d-half tid&1)
    {
        const int r  = tid >> 1;
        const int hf = tid & 1;
        const float* src = kvp + (size_t)(b * 128 + r) * 384 + h * 32 + hf * 16;
        float kb[16], vb[16];
#pragma unroll
        for (int j = 0; j < 4; j++) {
            float4 f = *(const float4*)(src + 4 * j);
            kb[4*j] = f.x; kb[4*j+1] = f.y; kb[4*j+2] = f.z; kb[4*j+3] = f.w;
            float4 g = *(const float4*)(src + 192 + 4 * j);
            vb[4*j] = g.x; vb[4*j+1] = g.y; vb[4*j+2] = g.z; vb[4*j+3] = g.w;
        }
        uint32_t kh[8], kl[8], vh[8], vl[8];
#pragma unroll
        for (int p = 0; p < 8; p++) {
            split_pair(kb[2*p], kb[2*p+1], kh[p], kl[p]);
            split_pair(vb[2*p], vb[2*p+1], vh[p], vl[p]);
        }
#pragma unroll
        for (int j = 0; j < 2; j++) {           // two 16B chunks per half-row
            int off = SWZ(r, hf * 2 + j);
            *(uint4*)(smem + 0     + off) = make_uint4(kh[4*j], kh[4*j+1], kh[4*j+2], kh[4*j+3]);
            *(uint4*)(smem + 8192  + off) = make_uint4(kl[4*j], kl[4*j+1], kl[4*j+2], kl[4*j+3]);
            *(uint4*)(smem + 16384 + off) = make_uint4(vh[4*j], vh[4*j+1], vh[4*j+2], vh[4*j+3]);
            *(uint4*)(smem + 24576 + off) = make_uint4(vl[4*j], vl[4*j+1], vl[4*j+2], vl[4*j+3]);
        }
    }

    for (int it = 0; it < 4; it++) {
        // ---- load Q block (128 rows), split bf16 ----
        {
            const int r  = tid >> 1;
            const int hf = tid & 1;
            const float* src = qp + (size_t)(b * 512 + it * 128 + r) * 192 + h * 32 + hf * 16;
            float qb[16];
#pragma unroll
            for (int j = 0; j < 4; j++) {
                float4 f = *(const float4*)(src + 4 * j);
                qb[4*j] = f.x; qb[4*j+1] = f.y; qb[4*j+2] = f.z; qb[4*j+3] = f.w;
            }
            uint32_t qh[8], ql[8];
#pragma unroll
            for (int p = 0; p < 8; p++)
                split_pair(qb[2*p], qb[2*p+1], qh[p], ql[p]);
#pragma unroll
            for (int j = 0; j < 2; j++) {
                int off = SWZ(r, hf * 2 + j);
                *(uint4*)(smem + 32768 + off) = make_uint4(qh[4*j], qh[4*j+1], qh[4*j+2], qh[4*j+3]);
                *(uint4*)(smem + 40960 + off) = make_uint4(ql[4*j], ql[4*j+1], ql[4*j+2], ql[4*j+3]);
            }
        }
        __syncthreads();

        const int m0 = w * 16;   // strip rows within this q-block

        // ---- Q A-fragments: [hilo][k-step s][4] ----
        uint32_t qa[2][2][4];
        {
            int rr = m0 + ((lane >> 3) & 1) * 8 + (lane & 7);
            int cb = lane >> 4;
#pragma unroll
            for (int s = 0; s < 2; s++) {
                int off = SWZ(rr, 2 * s + cb);
                ldsm4(qa[0][s], sQ_hi + off);
                ldsm4(qa[1][s], sQ_lo + off);
            }
        }

        // ---- S = Q K^T (16 x 128), 3 split terms ----
        float sacc[16][4];
#pragma unroll
        for (int n = 0; n < 16; n++)
#pragma unroll
            for (int e = 0; e < 4; e++) sacc[n][e] = 0.f;

#pragma unroll
        for (int n = 0; n < 16; n++) {
            int rr = n * 8 + (lane & 7);
            int off = SWZ(rr, lane >> 3);
            uint32_t kh[4], kl[4];
            ldsm4(kh, sK_hi + off);
            ldsm4(kl, sK_lo + off);
            mma16816(sacc[n], qa[0][0], kh[0], kh[1]);   // qh*kh  (d 0-15)
            mma16816(sacc[n], qa[0][1], kh[2], kh[3]);   //        (d 16-31)
            mma16816(sacc[n], qa[0][0], kl[0], kl[1]);   // qh*kl
            mma16816(sacc[n], qa[0][1], kl[2], kl[3]);
            mma16816(sacc[n], qa[1][0], kh[0], kh[1]);   // ql*kh
            mma16816(sacc[n], qa[1][1], kh[2], kh[3]);
        }

        // ---- bias + softmax ----
        const int qg1 = it * 128 + m0 + (lane >> 2);
        const int qg2 = qg1 + 8;
        const float* bp1 = g_bias + (size_t)h * 65536 + (size_t)qg1 * 128 + 2 * (lane & 3);
        const float* bp2 = g_bias + (size_t)h * 65536 + (size_t)qg2 * 128 + 2 * (lane & 3);
        float mx1 = -1e30f, mx2 = -1e30f;
#pragma unroll
        for (int n = 0; n < 16; n++) {
            float2 b1 = *(const float2*)(bp1 + 8 * n);
            float2 b2 = *(const float2*)(bp2 + 8 * n);
            sacc[n][0] += b1.x; sacc[n][1] += b1.y;
            sacc[n][2] += b2.x; sacc[n][3] += b2.y;
            mx1 = fmaxf(mx1, fmaxf(sacc[n][0], sacc[n][1]));
            mx2 = fmaxf(mx2, fmaxf(sacc[n][2], sacc[n][3]));
        }
        mx1 = fmaxf(mx1, __shfl_xor_sync(0xffffffffu, mx1, 1));
        mx1 = fmaxf(mx1, __shfl_xor_sync(0xffffffffu, mx1, 2));
        mx2 = fmaxf(mx2, __shfl_xor_sync(0xffffffffu, mx2, 1));
        mx2 = fmaxf(mx2, __shfl_xor_sync(0xffffffffu, mx2, 2));

        float sum1 = 0.f, sum2 = 0.f;
#pragma unroll
        for (int n = 0; n < 16; n++) {
            sacc[n][0] = __expf(sacc[n][0] - mx1); sum1 += sacc[n][0];
            sacc[n][1] = __expf(sacc[n][1] - mx1); sum1 += sacc[n][1];
            sacc[n][2] = __expf(sacc[n][2] - mx2); sum2 += sacc[n][2];
            sacc[n][3] = __expf(sacc[n][3] - mx2); sum2 += sacc[n][3];
        }
        sum1 += __shfl_xor_sync(0xffffffffu, sum1, 1);
        sum1 += __shfl_xor_sync(0xffffffffu, sum1, 2);
        sum2 += __shfl_xor_sync(0xffffffffu, sum2, 1);
        sum2 += __shfl_xor_sync(0xffffffffu, sum2, 2);
        const float inv1 = 1.0f / sum1;
        const float inv2 = 1.0f / sum2;

        // ---- P (unnormalized) -> A-fragments, split bf16 ----
        uint32_t pah[8][4], pal[8][4];
#pragma unroll
        for (int s = 0; s < 8; s++) {
            split_pair(sacc[2*s][0],   sacc[2*s][1],   pah[s][0], pal[s][0]);
            split_pair(sacc[2*s][2],   sacc[2*s][3],   pah[s][1], pal[s][1]);
            split_pair(sacc[2*s+1][0], sacc[2*s+1][1], pah[s][2], pal[s][2]);
            split_pair(sacc[2*s+1][2], sacc[2*s+1][3], pah[s][3], pal[s][3]);
        }

        // ---- O = P V (16 x 32), 3 split terms ----
        float oacc[4][4];
#pragma unroll
        for (int n = 0; n < 4; n++)
#pragma unroll
            for (int e = 0; e < 4; e++) oacc[n][e] = 0.f;

#pragma unroll
        for (int n = 0; n < 4; n++) {           // d-groups of 8
#pragma unroll
            for (int sh = 0; sh < 4; sh++) {    // key 32-chunks
                int rr = sh * 32 + (lane >> 3) * 8 + (lane & 7);
                int off = SWZ(rr, n);
                uint32_t vh[4], vl[4];
                ldsm4t(vh, sV_hi + off);
                ldsm4t(vl, sV_lo + off);
                int s0 = sh * 2, s1 = s0 + 1;
                mma16816(oacc[n], pah[s0], vh[0], vh[1]);   // Ph*Vh
                mma16816(oacc[n], pah[s1], vh[2], vh[3]);
                mma16816(oacc[n], pal[s0], vh[0], vh[1]);   // Pl*Vh
                mma16816(oacc[n], pal[s1], vh[2], vh[3]);
                mma16816(oacc[n], pah[s0], vl[0], vl[1]);   // Ph*Vl
                mma16816(oacc[n], pah[s1], vl[2], vl[3]);
            }
        }

        // ---- store O (normalize by deferred 1/sum) ----
        float* o1 = outp + (size_t)(b * 512 + qg1) * 192 + h * 32 + 2 * (lane & 3);
        float* o2 = outp + (size_t)(b * 512 + qg2) * 192 + h * 32 + 2 * (lane & 3);
#pragma unroll
        for (int n = 0; n < 4; n++) {
            *(float2*)(o1 + 8 * n) = make_float2(oacc[n][0] * inv1, oacc[n][1] * inv1);
            *(float2*)(o2 + 8 * n) = make_float2(oacc[n][2] * inv2, oacc[n][3] * inv2);
        }
        __syncthreads();   // before next block overwrites Q tiles
    }
}

// ---------------- launch ----------------
extern "C" void kernel_launch(void* const* d_in, const int* in_sizes, int n_in,
                              void* d_out, int out_size)
{
    const float* kv         = (const float*)d_in[0];
    const float* q          = (const float*)d_in[1];
    const float* w_kv       = (const float*)d_in[2];
    const float* b_kv       = (const float*)d_in[3];
    const float* w_q        = (const float*)d_in[4];
    const float* b_q        = (const float*)d_in[5];
    const float* w_proj     = (const float*)d_in[6];
    const float* b_proj     = (const float*)d_in[7];
    const float* bias_table = (const float*)d_in[8];
    const int*   rel_index  = (const int*)  d_in[9];
    float* out = (float*)d_out;

    float *p_kvp, *p_qp, *p_att;
    cudaGetSymbolAddress((void**)&p_kvp, g_kvp);
    cudaGetSymbolAddress((void**)&p_qp,  g_qp);
    cudaGetSymbolAddress((void**)&p_att, g_att);

    const float qscale = 0.17677669529663687f;  // 1/sqrt(32)

    bias_expand_kernel<<<1536, 256>>>(bias_table, rel_index);

    // kv projection: (32768 x 192) @ (192 x 384) + b_kv
    gemm_mma_kernel<<<dim3(3, 256), 256>>>(kv, w_kv, b_kv, p_kvp,
                                           32768, 192, 384, 1.0f);
    // q projection (scaled): (131072 x 96) @ (96 x 192) + b_q
    gemm_mma_kernel<<<dim3(2, 1024), 256>>>(q, w_q, b_q, p_qp,
                                            131072, 96, 192, qscale);
    // warp-MMA fused attention: one CTA per (batch, head)
    attn_mma_kernel<<<256 * 6, 256>>>(p_kvp, p_qp, p_att);

    // output projection: (131072 x 192) @ (192 x 96) + b_proj
    gemm_mma_kernel<<<dim3(1, 1024), 256>>>(p_att, w_proj, b_proj, out,
                                            131072, 192, 96, 1.0f);
}

// round 14
// speedup vs baseline: 2.1708x; 1.1025x over previous
#include <cuda_runtime.h>
#include <cuda_bf16.h>
#include <cstdint>

// ---------------- problem constants ----------------
// kv:  (256, 128, 192)   q: (256, 512, 96)
// w_kv:(192,384) b_kv:(384)  w_q:(96,192) b_q:(192)
// w_proj:(192,96) b_proj:(96)
// bias_table:(3375,6)  rel_index:(512,128) int32
// out: (256, 512, 96) fp32

// ---------------- scratch (device globals, allowed) ----------------
__device__ float g_kvp[32768u * 384u];    // kv proj   [B*128, 384]
__device__ float g_qp [131072u * 192u];   // q proj    [B*512, 192] (scaled)
__device__ float g_att[131072u * 192u];   // attn out  [B*512, 192]
__device__ float g_bias[6u * 512u * 128u];// expanded bias [h][q][k]

// ---------------- warp-MMA helpers (baseline ISA: sm_80+) ----------------
__device__ __forceinline__ uint32_t smem_u32(const void* p) {
    uint32_t a;
    asm("{ .reg .u64 t; cvta.to.shared.u64 t, %1; cvt.u32.u64 %0, t; }"
        : "=r"(a) : "l"(p));
    return a;
}
__device__ __forceinline__ void ldsm4(uint32_t* r, uint32_t addr) {
    asm volatile("ldmatrix.sync.aligned.m8n8.x4.shared.b16 {%0,%1,%2,%3}, [%4];"
        : "=r"(r[0]), "=r"(r[1]), "=r"(r[2]), "=r"(r[3]) : "r"(addr));
}
__device__ __forceinline__ void ldsm4t(uint32_t* r, uint32_t addr) {
    asm volatile("ldmatrix.sync.aligned.m8n8.x4.trans.shared.b16 {%0,%1,%2,%3}, [%4];"
        : "=r"(r[0]), "=r"(r[1]), "=r"(r[2]), "=r"(r[3]) : "r"(addr));
}
// D(f32) += A(bf16) * B(bf16), m16n8k16, A row-major, B col-major
__device__ __forceinline__ void mma16816(float* c, const uint32_t* a,
                                         uint32_t b0, uint32_t b1) {
    asm volatile(
        "mma.sync.aligned.m16n8k16.row.col.f32.bf16.bf16.f32 "
        "{%0,%1,%2,%3}, {%4,%5,%6,%7}, {%8,%9}, {%0,%1,%2,%3};"
        : "+f"(c[0]), "+f"(c[1]), "+f"(c[2]), "+f"(c[3])
        : "r"(a[0]), "r"(a[1]), "r"(a[2]), "r"(a[3]), "r"(b0), "r"(b1));
}
// split (x,y) into bf16 hi pair (truncation) + bf16 lo pair (rn of remainder)
// pair packing: low 16 bits = x, high 16 bits = y (ascending order).
__device__ __forceinline__ void split_pair(float x, float y,
                                           uint32_t& hi, uint32_t& lo) {
    uint32_t bx = __float_as_uint(x);
    uint32_t by = __float_as_uint(y);
    uint32_t hpk;
    asm("prmt.b32 %0, %1, %2, 0x7632;" : "=r"(hpk) : "r"(bx), "r"(by));
    float lx = x - __uint_as_float(bx & 0xFFFF0000u);
    float ly = y - __uint_as_float(by & 0xFFFF0000u);
    uint32_t lpk;
    asm("cvt.rn.bf16x2.f32 %0, %1, %2;" : "=r"(lpk) : "f"(ly), "f"(lx));
    hi = hpk; lo = lpk;
}

// swizzled 16B-chunk offset inside a 64B-row tile (4 chunks/row)
#define SWZ(row, c)  (((row) << 6) + ((((c) ^ (((row) >> 1) & 3))) << 4))
// swizzled 16B-chunk offset inside a 256B-row tile (16 chunks/row)
#define SWZW(row, c) (((row) << 8) + ((((c) ^ ((row) & 7))) << 4))

// ---------------- bias expansion ----------------
__global__ __launch_bounds__(256) void bias_expand_kernel(
    const float* __restrict__ table, const int* __restrict__ rel)
{
    int idx = blockIdx.x * 256 + threadIdx.x;       // 6*512*128 = 393216
    if (idx >= 6 * 512 * 128) return;
    int h  = idx >> 16;
    int qk = idx & 65535;
    g_bias[idx] = table[rel[qk] * 6 + h];
}

// ================= split-bf16 HMMA GEMM =================
// C[M,N] = (A[M,K] @ W[K,N] + bias[N]) * scale, fp32 in/out.
// CTA tile 128M x 128N, K in 32-chunks. 8 warps; warp = 16-row strip x 128 cols.
// 3 split terms: Ah*Wh + Al*Wh + Ah*Wl  (error ~2^-16).
__global__ __launch_bounds__(256) void gemm_mma_kernel(
    const float* __restrict__ A, const float* __restrict__ W,
    const float* __restrict__ bias, float* __restrict__ C,
    int M, int K, int N, float scale)
{
    __shared__ __align__(16) char smem[32768];
    const uint32_t sA_hi = smem_u32(smem);
    const uint32_t sA_lo = sA_hi + 8192;
    const uint32_t sW_hi = sA_hi + 16384;
    const uint32_t sW_lo = sA_hi + 24576;

    const int tid  = threadIdx.x;
    const int w    = tid >> 5;
    const int lane = tid & 31;
    const int bm = blockIdx.y * 128;
    const int bn = blockIdx.x * 128;

    float acc[16][4];
#pragma unroll
    for (int n = 0; n < 16; n++)
#pragma unroll
        for (int e = 0; e < 4; e++) acc[n][e] = 0.f;

    const int m0 = w * 16;
    const int arr = m0 + ((lane >> 3) & 1) * 8 + (lane & 7);
    const int acb = lane >> 4;

    for (int k0 = 0; k0 < K; k0 += 32) {
        // ---- load A chunk: thread (row tid>>1, k-half tid&1) ----
        {
            const int r  = tid >> 1;
            const int hf = tid & 1;
            const float* src = A + (size_t)(bm + r) * K + k0 + hf * 16;
            float av[16];
#pragma unroll
            for (int j = 0; j < 4; j++) {
                float4 f = *(const float4*)(src + 4 * j);
                av[4*j] = f.x; av[4*j+1] = f.y; av[4*j+2] = f.z; av[4*j+3] = f.w;
            }
            uint32_t hi[8], lo[8];
#pragma unroll
            for (int p = 0; p < 8; p++)
                split_pair(av[2*p], av[2*p+1], hi[p], lo[p]);
#pragma unroll
            for (int j = 0; j < 2; j++) {
                int off = SWZ(r, hf * 2 + j);
                *(uint4*)(smem + 0    + off) = make_uint4(hi[4*j], hi[4*j+1], hi[4*j+2], hi[4*j+3]);
                *(uint4*)(smem + 8192 + off) = make_uint4(lo[4*j], lo[4*j+1], lo[4*j+2], lo[4*j+3]);
            }
        }
        // ---- load W chunk: 32 k-rows x 128 n; unit = 8 n-values ----
#pragma unroll
        for (int i = 0; i < 2; i++) {
            int lin = tid + 256 * i;          // 0..511
            int kk  = lin >> 4;               // 0..31
            int c   = lin & 15;               // n-octet
            int n0  = bn + 8 * c;
            float wv[8];
            if (n0 + 4 <= N) {
                float4 f = *(const float4*)(W + (size_t)(k0 + kk) * N + n0);
                wv[0]=f.x; wv[1]=f.y; wv[2]=f.z; wv[3]=f.w;
            } else { wv[0]=wv[1]=wv[2]=wv[3]=0.f; }
            if (n0 + 8 <= N) {
                float4 f = *(const float4*)(W + (size_t)(k0 + kk) * N + n0 + 4);
                wv[4]=f.x; wv[5]=f.y; wv[6]=f.z; wv[7]=f.w;
            } else { wv[4]=wv[5]=wv[6]=wv[7]=0.f; }
            uint32_t hi[4], lo[4];
#pragma unroll
            for (int p = 0; p < 4; p++)
                split_pair(wv[2*p], wv[2*p+1], hi[p], lo[p]);
            int off = SWZW(kk, c);
            *(uint4*)(smem + 16384 + off) = make_uint4(hi[0], hi[1], hi[2], hi[3]);
            *(uint4*)(smem + 24576 + off) = make_uint4(lo[0], lo[1], lo[2], lo[3]);
        }
        __syncthreads();

        // ---- A fragments: [hilo][k-step][4] ----
        uint32_t ah[2][4], al[2][4];
#pragma unroll
        for (int s = 0; s < 2; s++) {
            int off = SWZ(arr, 2 * s + acb);
            ldsm4(ah[s], sA_hi + off);
            ldsm4(al[s], sA_lo + off);
        }

        // ---- per n-octet: ldsm4t W (4 k-octets), 6 mma ----
#pragma unroll
        for (int no = 0; no < 16; no++) {
            int off = SWZW(lane, no);         // rows = lane (0..31), chunk no
            uint32_t wh[4], wl[4];
            ldsm4t(wh, sW_hi + off);
            ldsm4t(wl, sW_lo + off);
            mma16816(acc[no], ah[0], wh[0], wh[1]);   // Ah*Wh  k 0-15
            mma16816(acc[no], ah[1], wh[2], wh[3]);   //        k 16-31
            mma16816(acc[no], al[0], wh[0], wh[1]);   // Al*Wh
            mma16816(acc[no], al[1], wh[2], wh[3]);
            mma16816(acc[no], ah[0], wl[0], wl[1]);   // Ah*Wl
            mma16816(acc[no], ah[1], wl[2], wl[3]);
        }
        __syncthreads();
    }

    // ---- epilogue: bias + scale, masked float2 stores ----
    const int r1 = bm + m0 + (lane >> 2);
    const int r2 = r1 + 8;
    const int cb2 = 2 * (lane & 3);
#pragma unroll
    for (int no = 0; no < 16; no++) {
        int col = bn + 8 * no + cb2;
        if (col < N) {
            float2 bv = *(const float2*)(bias + col);
            *(float2*)(C + (size_t)r1 * N + col) =
                make_float2((acc[no][0] + bv.x) * scale, (acc[no][1] + bv.y) * scale);
            *(float2*)(C + (size_t)r2 * N + col) =
                make_float2((acc[no][2] + bv.x) * scale, (acc[no][3] + bv.y) * scale);
        }
    }
}

// ================= warp-MMA attention (split bf16, HMMA) =================
// One CTA per (b, h); 256 threads = 8 warps. 4 outer q-blocks of 128 rows;
// each warp owns one 16-row strip per block.
// R13: lazy P-conversion (sh-outer AV loop) cuts live regs so 2 CTAs/SM fit;
// __launch_bounds__(256, 2) pins the 128-reg budget.
__global__ __launch_bounds__(256, 2) void attn_mma_kernel(
    const float* __restrict__ kvp,    // [B*128, 384]
    const float* __restrict__ qp,     // [B*512, 192]  (pre-scaled)
    float* __restrict__ outp)         // [B*512, 192]
{
    __shared__ __align__(16) char smem[49152];
    const uint32_t sK_hi = smem_u32(smem);
    const uint32_t sK_lo = sK_hi + 8192;
    const uint32_t sV_hi = sK_hi + 16384;
    const uint32_t sV_lo = sK_hi + 24576;
    const uint32_t sQ_hi = sK_hi + 32768;
    const uint32_t sQ_lo = sK_hi + 40960;

    const int tid  = threadIdx.x;
    const int w    = tid >> 5;
    const int lane = tid & 31;
    const int b = blockIdx.x / 6;
    const int h = blockIdx.x % 6;

    // ---- prologue: K,V -> smem, split bf16. thread = (row tid>>1, d-half tid&1)
    {
        const int r  = tid >> 1;
        const int hf = tid & 1;
        const float* src = kvp + (size_t)(b * 128 + r) * 384 + h * 32 + hf * 16;
        float kb[16], vb[16];
#pragma unroll
        for (int j = 0; j < 4; j++) {
            float4 f = *(const float4*)(src + 4 * j);
            kb[4*j] = f.x; kb[4*j+1] = f.y; kb[4*j+2] = f.z; kb[4*j+3] = f.w;
            float4 g = *(const float4*)(src + 192 + 4 * j);
            vb[4*j] = g.x; vb[4*j+1] = g.y; vb[4*j+2] = g.z; vb[4*j+3] = g.w;
        }
        uint32_t kh[8], kl[8], vh[8], vl[8];
#pragma unroll
        for (int p = 0; p < 8; p++) {
            split_pair(kb[2*p], kb[2*p+1], kh[p], kl[p]);
            split_pair(vb[2*p], vb[2*p+1], vh[p], vl[p]);
        }
#pragma unroll
        for (int j = 0; j < 2; j++) {           // two 16B chunks per half-row
            int off = SWZ(r, hf * 2 + j);
            *(uint4*)(smem + 0     + off) = make_uint4(kh[4*j], kh[4*j+1], kh[4*j+2], kh[4*j+3]);
            *(uint4*)(smem + 8192  + off) = make_uint4(kl[4*j], kl[4*j+1], kl[4*j+2], kl[4*j+3]);
            *(uint4*)(smem + 16384 + off) = make_uint4(vh[4*j], vh[4*j+1], vh[4*j+2], vh[4*j+3]);
            *(uint4*)(smem + 24576 + off) = make_uint4(vl[4*j], vl[4*j+1], vl[4*j+2], vl[4*j+3]);
        }
    }

    for (int it = 0; it < 4; it++) {
        // ---- load Q block (128 rows), split bf16 ----
        {
            const int r  = tid >> 1;
            const int hf = tid & 1;
            const float* src = qp + (size_t)(b * 512 + it * 128 + r) * 192 + h * 32 + hf * 16;
            float qb[16];
#pragma unroll
            for (int j = 0; j < 4; j++) {
                float4 f = *(const float4*)(src + 4 * j);
                qb[4*j] = f.x; qb[4*j+1] = f.y; qb[4*j+2] = f.z; qb[4*j+3] = f.w;
            }
            uint32_t qh[8], ql[8];
#pragma unroll
            for (int p = 0; p < 8; p++)
                split_pair(qb[2*p], qb[2*p+1], qh[p], ql[p]);
#pragma unroll
            for (int j = 0; j < 2; j++) {
                int off = SWZ(r, hf * 2 + j);
                *(uint4*)(smem + 32768 + off) = make_uint4(qh[4*j], qh[4*j+1], qh[4*j+2], qh[4*j+3]);
                *(uint4*)(smem + 40960 + off) = make_uint4(ql[4*j], ql[4*j+1], ql[4*j+2], ql[4*j+3]);
            }
        }
        __syncthreads();

        const int m0 = w * 16;   // strip rows within this q-block

        // ---- Q A-fragments: [hilo][k-step s][4] ----
        uint32_t qa[2][2][4];
        {
            int rr = m0 + ((lane >> 3) & 1) * 8 + (lane & 7);
            int cb = lane >> 4;
#pragma unroll
            for (int s = 0; s < 2; s++) {
                int off = SWZ(rr, 2 * s + cb);
                ldsm4(qa[0][s], sQ_hi + off);
                ldsm4(qa[1][s], sQ_lo + off);
            }
        }

        // ---- S = Q K^T (16 x 128), 3 split terms ----
        float sacc[16][4];
#pragma unroll
        for (int n = 0; n < 16; n++)
#pragma unroll
            for (int e = 0; e < 4; e++) sacc[n][e] = 0.f;

#pragma unroll
        for (int n = 0; n < 16; n++) {
            int rr = n * 8 + (lane & 7);
            int off = SWZ(rr, lane >> 3);
            uint32_t kh[4], kl[4];
            ldsm4(kh, sK_hi + off);
            ldsm4(kl, sK_lo + off);
            mma16816(sacc[n], qa[0][0], kh[0], kh[1]);   // qh*kh  (d 0-15)
            mma16816(sacc[n], qa[0][1], kh[2], kh[3]);   //        (d 16-31)
            mma16816(sacc[n], qa[0][0], kl[0], kl[1]);   // qh*kl
            mma16816(sacc[n], qa[0][1], kl[2], kl[3]);
            mma16816(sacc[n], qa[1][0], kh[0], kh[1]);   // ql*kh
            mma16816(sacc[n], qa[1][1], kh[2], kh[3]);
        }

        // ---- bias + softmax ----
        const int qg1 = it * 128 + m0 + (lane >> 2);
        const int qg2 = qg1 + 8;
        const float* bp1 = g_bias + (size_t)h * 65536 + (size_t)qg1 * 128 + 2 * (lane & 3);
        const float* bp2 = g_bias + (size_t)h * 65536 + (size_t)qg2 * 128 + 2 * (lane & 3);
        float mx1 = -1e30f, mx2 = -1e30f;
#pragma unroll
        for (int n = 0; n < 16; n++) {
            float2 b1 = *(const float2*)(bp1 + 8 * n);
            float2 b2 = *(const float2*)(bp2 + 8 * n);
            sacc[n][0] += b1.x; sacc[n][1] += b1.y;
            sacc[n][2] += b2.x; sacc[n][3] += b2.y;
            mx1 = fmaxf(mx1, fmaxf(sacc[n][0], sacc[n][1]));
            mx2 = fmaxf(mx2, fmaxf(sacc[n][2], sacc[n][3]));
        }
        mx1 = fmaxf(mx1, __shfl_xor_sync(0xffffffffu, mx1, 1));
        mx1 = fmaxf(mx1, __shfl_xor_sync(0xffffffffu, mx1, 2));
        mx2 = fmaxf(mx2, __shfl_xor_sync(0xffffffffu, mx2, 1));
        mx2 = fmaxf(mx2, __shfl_xor_sync(0xffffffffu, mx2, 2));

        float sum1 = 0.f, sum2 = 0.f;
#pragma unroll
        for (int n = 0; n < 16; n++) {
            sacc[n][0] = __expf(sacc[n][0] - mx1); sum1 += sacc[n][0];
            sacc[n][1] = __expf(sacc[n][1] - mx1); sum1 += sacc[n][1];
            sacc[n][2] = __expf(sacc[n][2] - mx2); sum2 += sacc[n][2];
            sacc[n][3] = __expf(sacc[n][3] - mx2); sum2 += sacc[n][3];
        }
        sum1 += __shfl_xor_sync(0xffffffffu, sum1, 1);
        sum1 += __shfl_xor_sync(0xffffffffu, sum1, 2);
        sum2 += __shfl_xor_sync(0xffffffffu, sum2, 1);
        sum2 += __shfl_xor_sync(0xffffffffu, sum2, 2);
        const float inv1 = 1.0f / sum1;
        const float inv2 = 1.0f / sum2;

        // ---- O = P V (16 x 32), 3 split terms; lazy P-conversion per key
        //      32-chunk (sh outer): only 16 P-regs live, sacc rows die as used.
        float oacc[4][4];
#pragma unroll
        for (int n = 0; n < 4; n++)
#pragma unroll
            for (int e = 0; e < 4; e++) oacc[n][e] = 0.f;

#pragma unroll
        for (int sh = 0; sh < 4; sh++) {        // key 32-chunks
            // convert sacc[4sh .. 4sh+3] -> A-frags for this chunk
            uint32_t pah0[4], pal0[4], pah1[4], pal1[4];
            split_pair(sacc[4*sh+0][0], sacc[4*sh+0][1], pah0[0], pal0[0]);
            split_pair(sacc[4*sh+0][2], sacc[4*sh+0][3], pah0[1], pal0[1]);
            split_pair(sacc[4*sh+1][0], sacc[4*sh+1][1], pah0[2], pal0[2]);
            split_pair(sacc[4*sh+1][2], sacc[4*sh+1][3], pah0[3], pal0[3]);
            split_pair(sacc[4*sh+2][0], sacc[4*sh+2][1], pah1[0], pal1[0]);
            split_pair(sacc[4*sh+2][2], sacc[4*sh+2][3], pah1[1], pal1[1]);
            split_pair(sacc[4*sh+3][0], sacc[4*sh+3][1], pah1[2], pal1[2]);
            split_pair(sacc[4*sh+3][2], sacc[4*sh+3][3], pah1[3], pal1[3]);

            int rr = sh * 32 + (lane >> 3) * 8 + (lane & 7);
#pragma unroll
            for (int n = 0; n < 4; n++) {       // d-groups of 8
                int off = SWZ(rr, n);
                uint32_t vh[4], vl[4];
                ldsm4t(vh, sV_hi + off);
                ldsm4t(vl, sV_lo + off);
                mma16816(oacc[n], pah0, vh[0], vh[1]);   // Ph*Vh
                mma16816(oacc[n], pah1, vh[2], vh[3]);
                mma16816(oacc[n], pal0, vh[0], vh[1]);   // Pl*Vh
                mma16816(oacc[n], pal1, vh[2], vh[3]);
                mma16816(oacc[n], pah0, vl[0], vl[1]);   // Ph*Vl
                mma16816(oacc[n], pah1, vl[2], vl[3]);
            }
        }

        // ---- store O (normalize by deferred 1/sum) ----
        float* o1 = outp + (size_t)(b * 512 + qg1) * 192 + h * 32 + 2 * (lane & 3);
        float* o2 = outp + (size_t)(b * 512 + qg2) * 192 + h * 32 + 2 * (lane & 3);
#pragma unroll
        for (int n = 0; n < 4; n++) {
            *(float2*)(o1 + 8 * n) = make_float2(oacc[n][0] * inv1, oacc[n][1] * inv1);
            *(float2*)(o2 + 8 * n) = make_float2(oacc[n][2] * inv2, oacc[n][3] * inv2);
        }
        __syncthreads();   // before next block overwrites Q tiles
    }
}

// ---------------- launch ----------------
extern "C" void kernel_launch(void* const* d_in, const int* in_sizes, int n_in,
                              void* d_out, int out_size)
{
    const float* kv         = (const float*)d_in[0];
    const float* q          = (const float*)d_in[1];
    const float* w_kv       = (const float*)d_in[2];
    const float* b_kv       = (const float*)d_in[3];
    const float* w_q        = (const float*)d_in[4];
    const float* b_q        = (const float*)d_in[5];
    const float* w_proj     = (const float*)d_in[6];
    const float* b_proj     = (const float*)d_in[7];
    const float* bias_table = (const float*)d_in[8];
    const int*   rel_index  = (const int*)  d_in[9];
    float* out = (float*)d_out;

    float *p_kvp, *p_qp, *p_att;
    cudaGetSymbolAddress((void**)&p_kvp, g_kvp);
    cudaGetSymbolAddress((void**)&p_qp,  g_qp);
    cudaGetSymbolAddress((void**)&p_att, g_att);

    const float qscale = 0.17677669529663687f;  // 1/sqrt(32)

    bias_expand_kernel<<<1536, 256>>>(bias_table, rel_index);

    // kv projection: (32768 x 192) @ (192 x 384) + b_kv
    gemm_mma_kernel<<<dim3(3, 256), 256>>>(kv, w_kv, b_kv, p_kvp,
                                           32768, 192, 384, 1.0f);
    // q projection (scaled): (131072 x 96) @ (96 x 192) + b_q
    gemm_mma_kernel<<<dim3(2, 1024), 256>>>(q, w_q, b_q, p_qp,
                                            131072, 96, 192, qscale);
    // warp-MMA fused attention: one CTA per (batch, head)
    attn_mma_kernel<<<256 * 6, 256>>>(p_kvp, p_qp, p_att);

    // output projection: (131072 x 192) @ (192 x 96) + b_proj
    gemm_mma_kernel<<<dim3(1, 1024), 256>>>(p_att, w_proj, b_proj, out,
                                            131072, 192, 96, 1.0f);
}

// round 15
// speedup vs baseline: 3.0640x; 1.4114x over previous
#include <cuda_runtime.h>
#include <cuda_bf16.h>
#include <cstdint>

// ---------------- problem constants ----------------
// kv:  (256, 128, 192)   q: (256, 512, 96)
// w_kv:(192,384) b_kv:(384)  w_q:(96,192) b_q:(192)
// w_proj:(192,96) b_proj:(96)
// bias_table:(3375,6)  rel_index:(512,128) int32
// out: (256, 512, 96) fp32

// ---------------- scratch (device globals, allowed) ----------------
__device__ float g_kvp[32768u * 384u];    // kv proj   [B*128, 384]
__device__ float g_att[131072u * 192u];   // attn out  [B*512, 192]
__device__ float g_bias[6u * 512u * 128u];// expanded bias [h][q][k]

// ---------------- warp-MMA helpers (baseline ISA: sm_80+) ----------------
__device__ __forceinline__ uint32_t smem_u32(const void* p) {
    uint32_t a;
    asm("{ .reg .u64 t; cvta.to.shared.u64 t, %1; cvt.u32.u64 %0, t; }"
        : "=r"(a) : "l"(p));
    return a;
}
__device__ __forceinline__ void ldsm4(uint32_t* r, uint32_t addr) {
    asm volatile("ldmatrix.sync.aligned.m8n8.x4.shared.b16 {%0,%1,%2,%3}, [%4];"
        : "=r"(r[0]), "=r"(r[1]), "=r"(r[2]), "=r"(r[3]) : "r"(addr));
}
__device__ __forceinline__ void ldsm4t(uint32_t* r, uint32_t addr) {
    asm volatile("ldmatrix.sync.aligned.m8n8.x4.trans.shared.b16 {%0,%1,%2,%3}, [%4];"
        : "=r"(r[0]), "=r"(r[1]), "=r"(r[2]), "=r"(r[3]) : "r"(addr));
}
// D(f32) += A(bf16) * B(bf16), m16n8k16, A row-major, B col-major
__device__ __forceinline__ void mma16816(float* c, const uint32_t* a,
                                         uint32_t b0, uint32_t b1) {
    asm volatile(
        "mma.sync.aligned.m16n8k16.row.col.f32.bf16.bf16.f32 "
        "{%0,%1,%2,%3}, {%4,%5,%6,%7}, {%8,%9}, {%0,%1,%2,%3};"
        : "+f"(c[0]), "+f"(c[1]), "+f"(c[2]), "+f"(c[3])
        : "r"(a[0]), "r"(a[1]), "r"(a[2]), "r"(a[3]), "r"(b0), "r"(b1));
}
// split (x,y) into bf16 hi pair (truncation) + bf16 lo pair (rn of remainder)
__device__ __forceinline__ void split_pair(float x, float y,
                                           uint32_t& hi, uint32_t& lo) {
    uint32_t bx = __float_as_uint(x);
    uint32_t by = __float_as_uint(y);
    uint32_t hpk;
    asm("prmt.b32 %0, %1, %2, 0x7632;" : "=r"(hpk) : "r"(bx), "r"(by));
    float lx = x - __uint_as_float(bx & 0xFFFF0000u);
    float ly = y - __uint_as_float(by & 0xFFFF0000u);
    uint32_t lpk;
    asm("cvt.rn.bf16x2.f32 %0, %1, %2;" : "=r"(lpk) : "f"(ly), "f"(lx));
    hi = hpk; lo = lpk;
}

// swizzled 16B-chunk offset inside a 64B-row tile (4 chunks/row)
#define SWZ(row, c)  (((row) << 6) + ((((c) ^ (((row) >> 1) & 3))) << 4))
// swizzled 16B-chunk offset inside a 256B-row tile (16 chunks/row)
#define SWZW(row, c) (((row) << 8) + ((((c) ^ ((row) & 7))) << 4))

// ---------------- bias expansion ----------------
__global__ __launch_bounds__(256) void bias_expand_kernel(
    const float* __restrict__ table, const int* __restrict__ rel)
{
    int idx = blockIdx.x * 256 + threadIdx.x;       // 6*512*128 = 393216
    if (idx >= 6 * 512 * 128) return;
    int h  = idx >> 16;
    int qk = idx & 65535;
    g_bias[idx] = table[rel[qk] * 6 + h];
}

// ================= split-bf16 HMMA GEMM (N-tile = 96, exact) =================
// C[M,N] = (A[M,K] @ W[K,N] + bias[N]) * scale, fp32 in/out.
// CTA tile 128M x 96N, K in 32-chunks. 8 warps; warp = 16-row strip x 96 cols.
// 3 split terms: Ah*Wh + Al*Wh + Ah*Wl.
// Requires: M % 128 == 0, K % 32 == 0, N % 96 == 0 (all shapes here comply).
__global__ __launch_bounds__(256) void gemm_mma_kernel(
    const float* __restrict__ A, const float* __restrict__ W,
    const float* __restrict__ bias, float* __restrict__ C,
    int M, int K, int N, float scale)
{
    __shared__ __align__(16) char smem[32768];
    const uint32_t sA_hi = smem_u32(smem);
    const uint32_t sA_lo = sA_hi + 8192;
    const uint32_t sW_hi = sA_hi + 16384;
    const uint32_t sW_lo = sA_hi + 24576;

    const int tid  = threadIdx.x;
    const int w    = tid >> 5;
    const int lane = tid & 31;
    const int bm = blockIdx.y * 128;
    const int bn = blockIdx.x * 96;

    float acc[12][4];
#pragma unroll
    for (int n = 0; n < 12; n++)
#pragma unroll
        for (int e = 0; e < 4; e++) acc[n][e] = 0.f;

    const int m0 = w * 16;
    const int arr = m0 + ((lane >> 3) & 1) * 8 + (lane & 7);
    const int acb = lane >> 4;

    for (int k0 = 0; k0 < K; k0 += 32) {
        // ---- load A chunk: thread (row tid>>1, k-half tid&1) ----
        {
            const int r  = tid >> 1;
            const int hf = tid & 1;
            const float* src = A + (size_t)(bm + r) * K + k0 + hf * 16;
            float av[16];
#pragma unroll
            for (int j = 0; j < 4; j++) {
                float4 f = *(const float4*)(src + 4 * j);
                av[4*j] = f.x; av[4*j+1] = f.y; av[4*j+2] = f.z; av[4*j+3] = f.w;
            }
            uint32_t hi[8], lo[8];
#pragma unroll
            for (int p = 0; p < 8; p++)
                split_pair(av[2*p], av[2*p+1], hi[p], lo[p]);
#pragma unroll
            for (int j = 0; j < 2; j++) {
                int off = SWZ(r, hf * 2 + j);
                *(uint4*)(smem + 0    + off) = make_uint4(hi[4*j], hi[4*j+1], hi[4*j+2], hi[4*j+3]);
                *(uint4*)(smem + 8192 + off) = make_uint4(lo[4*j], lo[4*j+1], lo[4*j+2], lo[4*j+3]);
            }
        }
        // ---- load W chunk: 32 k-rows x 96 n; unit = 8 n-values (384 units) ----
#pragma unroll
        for (int i = 0; i < 2; i++) {
            int lin = tid + 256 * i;          // 0..511
            if (lin < 384) {
                int kk  = lin / 12;           // 0..31
                int c   = lin - kk * 12;      // n-octet 0..11
                const float* src = W + (size_t)(k0 + kk) * N + bn + 8 * c;
                float4 f0 = *(const float4*)(src);
                float4 f1 = *(const float4*)(src + 4);
                uint32_t hi[4], lo[4];
                split_pair(f0.x, f0.y, hi[0], lo[0]);
                split_pair(f0.z, f0.w, hi[1], lo[1]);
                split_pair(f1.x, f1.y, hi[2], lo[2]);
                split_pair(f1.z, f1.w, hi[3], lo[3]);
                int off = SWZW(kk, c);
                *(uint4*)(smem + 16384 + off) = make_uint4(hi[0], hi[1], hi[2], hi[3]);
                *(uint4*)(smem + 24576 + off) = make_uint4(lo[0], lo[1], lo[2], lo[3]);
            }
        }
        __syncthreads();

        // ---- A fragments: [hilo][k-step][4] ----
        uint32_t ah[2][4], al[2][4];
#pragma unroll
        for (int s = 0; s < 2; s++) {
            int off = SWZ(arr, 2 * s + acb);
            ldsm4(ah[s], sA_hi + off);
            ldsm4(al[s], sA_lo + off);
        }

        // ---- per n-octet: ldsm4t W (4 k-octets), 6 mma ----
#pragma unroll
        for (int no = 0; no < 12; no++) {
            int off = SWZW(lane, no);
            uint32_t wh[4], wl[4];
            ldsm4t(wh, sW_hi + off);
            ldsm4t(wl, sW_lo + off);
            mma16816(acc[no], ah[0], wh[0], wh[1]);   // Ah*Wh  k 0-15
            mma16816(acc[no], ah[1], wh[2], wh[3]);   //        k 16-31
            mma16816(acc[no], al[0], wh[0], wh[1]);   // Al*Wh
            mma16816(acc[no], al[1], wh[2], wh[3]);
            mma16816(acc[no], ah[0], wl[0], wl[1]);   // Ah*Wl
            mma16816(acc[no], ah[1], wl[2], wl[3]);
        }
        __syncthreads();
    }

    // ---- epilogue: bias + scale (N exact multiple of 96, no masks) ----
    const int r1 = bm + m0 + (lane >> 2);
    const int r2 = r1 + 8;
    const int cb2 = 2 * (lane & 3);
#pragma unroll
    for (int no = 0; no < 12; no++) {
        int col = bn + 8 * no + cb2;
        float2 bv = *(const float2*)(bias + col);
        *(float2*)(C + (size_t)r1 * N + col) =
            make_float2((acc[no][0] + bv.x) * scale, (acc[no][1] + bv.y) * scale);
        *(float2*)(C + (size_t)r2 * N + col) =
            make_float2((acc[no][2] + bv.x) * scale, (acc[no][3] + bv.y) * scale);
    }
}

// ================= warp-MMA attention with fused q-projection =================
// One CTA per (b, h); 256 threads = 8 warps; 4 q-blocks of 128 rows, warp = 16-row strip.
// NEW (R14): Q is computed inline: facc = q(16x96) @ w_q_head(96x32) via 3-term
// HMMA (A-frags fed straight from gmem — q is L2-resident), then
// (facc + b_q)*qscale C-frags convert DIRECTLY into QK A-frags (C->A identity).
// No Q smem tiles, no per-iteration __syncthreads.
// smem: Khi 8K | Klo 8K | Vhi 8K | Vlo 8K | WQhi 6K | WQlo 6K = 44 KB static.
__global__ __launch_bounds__(256, 2) void attn_mma_kernel(
    const float* __restrict__ kvp,    // [B*128, 384]
    const float* __restrict__ qraw,   // [B*512, 96]
    const float* __restrict__ w_q,    // [96, 192]
    const float* __restrict__ b_q,    // [192]
    float* __restrict__ outp)         // [B*512, 192]
{
    __shared__ __align__(16) char smem[45056];
    const uint32_t sK_hi = smem_u32(smem);
    const uint32_t sK_lo = sK_hi + 8192;
    const uint32_t sV_hi = sK_hi + 16384;
    const uint32_t sV_lo = sK_hi + 24576;
    const uint32_t sWQ_hi = sK_hi + 32768;
    const uint32_t sWQ_lo = sK_hi + 38912;

    const int tid  = threadIdx.x;
    const int w    = tid >> 5;
    const int lane = tid & 31;
    const int b = blockIdx.x / 6;
    const int h = blockIdx.x % 6;

    const float qscale = 0.17677669529663687f;  // 1/sqrt(32)

    // ---- prologue: K,V -> smem, split bf16 ----
    {
        const int r  = tid >> 1;
        const int hf = tid & 1;
        const float* src = kvp + (size_t)(b * 128 + r) * 384 + h * 32 + hf * 16;
        float kb[16], vb[16];
#pragma unroll
        for (int j = 0; j < 4; j++) {
            float4 f = *(const float4*)(src + 4 * j);
            kb[4*j] = f.x; kb[4*j+1] = f.y; kb[4*j+2] = f.z; kb[4*j+3] = f.w;
            float4 g = *(const float4*)(src + 192 + 4 * j);
            vb[4*j] = g.x; vb[4*j+1] = g.y; vb[4*j+2] = g.z; vb[4*j+3] = g.w;
        }
        uint32_t kh[8], kl[8], vh[8], vl[8];
#pragma unroll
        for (int p = 0; p < 8; p++) {
            split_pair(kb[2*p], kb[2*p+1], kh[p], kl[p]);
            split_pair(vb[2*p], vb[2*p+1], vh[p], vl[p]);
        }
#pragma unroll
        for (int j = 0; j < 2; j++) {
            int off = SWZ(r, hf * 2 + j);
            *(uint4*)(smem + 0     + off) = make_uint4(kh[4*j], kh[4*j+1], kh[4*j+2], kh[4*j+3]);
            *(uint4*)(smem + 8192  + off) = make_uint4(kl[4*j], kl[4*j+1], kl[4*j+2], kl[4*j+3]);
            *(uint4*)(smem + 16384 + off) = make_uint4(vh[4*j], vh[4*j+1], vh[4*j+2], vh[4*j+3]);
            *(uint4*)(smem + 24576 + off) = make_uint4(vl[4*j], vl[4*j+1], vl[4*j+2], vl[4*j+3]);
        }
    }
    // ---- prologue: w_q head slice (96 x 32) -> smem, split bf16 (V-style tile) ----
    if (tid < 192) {
        const int r  = tid >> 1;      // k-row 0..95
        const int hf = tid & 1;       // 16-col half
        const float* src = w_q + (size_t)r * 192 + h * 32 + hf * 16;
        float wv[16];
#pragma unroll
        for (int j = 0; j < 4; j++) {
            float4 f = *(const float4*)(src + 4 * j);
            wv[4*j] = f.x; wv[4*j+1] = f.y; wv[4*j+2] = f.z; wv[4*j+3] = f.w;
        }
        uint32_t hi[8], lo[8];
#pragma unroll
        for (int p = 0; p < 8; p++)
            split_pair(wv[2*p], wv[2*p+1], hi[p], lo[p]);
#pragma unroll
        for (int j = 0; j < 2; j++) {
            int off = SWZ(r, hf * 2 + j);
            *(uint4*)(smem + 32768 + off) = make_uint4(hi[4*j], hi[4*j+1], hi[4*j+2], hi[4*j+3]);
            *(uint4*)(smem + 38912 + off) = make_uint4(lo[4*j], lo[4*j+1], lo[4*j+2], lo[4*j+3]);
        }
    }
    __syncthreads();   // only block-wide sync: all smem is read-only after this

    const int m0 = w * 16;

    for (int it = 0; it < 4; it++) {
        // ---- fused q-projection: facc(16x32) = q(16x96) @ w_q_head, 3 terms ----
        float facc[4][4];
#pragma unroll
        for (int n = 0; n < 4; n++)
#pragma unroll
            for (int e = 0; e < 4; e++) facc[n][e] = 0.f;

        const float* qbase = qraw
            + (size_t)(b * 512 + it * 128 + m0 + (lane >> 2)) * 96 + 2 * (lane & 3);
#pragma unroll
        for (int kq = 0; kq < 3; kq++) {
            uint32_t ah[2][4], al[2][4];
#pragma unroll
            for (int s = 0; s < 2; s++) {
                int kb = 32 * kq + 16 * s;
                float2 x0 = *(const float2*)(qbase + kb);
                float2 x1 = *(const float2*)(qbase + 8 * 96 + kb);
                float2 x2 = *(const float2*)(qbase + kb + 8);
                float2 x3 = *(const float2*)(qbase + 8 * 96 + kb + 8);
                split_pair(x0.x, x0.y, ah[s][0], al[s][0]);
                split_pair(x1.x, x1.y, ah[s][1], al[s][1]);
                split_pair(x2.x, x2.y, ah[s][2], al[s][2]);
                split_pair(x3.x, x3.y, ah[s][3], al[s][3]);
            }
            int rr = kq * 32 + (lane >> 3) * 8 + (lane & 7);
#pragma unroll
            for (int no = 0; no < 4; no++) {
                int off = SWZ(rr, no);
                uint32_t wh[4], wl[4];
                ldsm4t(wh, sWQ_hi + off);
                ldsm4t(wl, sWQ_lo + off);
                mma16816(facc[no], ah[0], wh[0], wh[1]);   // Ah*Wh
                mma16816(facc[no], ah[1], wh[2], wh[3]);
                mma16816(facc[no], al[0], wh[0], wh[1]);   // Al*Wh
                mma16816(facc[no], al[1], wh[2], wh[3]);
                mma16816(facc[no], ah[0], wl[0], wl[1]);   // Ah*Wl
                mma16816(facc[no], ah[1], wl[2], wl[3]);
            }
        }

        // ---- (facc + b_q) * qscale  ->  QK A-frags (C->A layout identity) ----
        uint32_t qa[2][2][4];
#pragma unroll
        for (int n = 0; n < 4; n++) {
            float2 bq = *(const float2*)(b_q + h * 32 + 8 * n + 2 * (lane & 3));
            float v0 = (facc[n][0] + bq.x) * qscale;
            float v1 = (facc[n][1] + bq.y) * qscale;
            float v2 = (facc[n][2] + bq.x) * qscale;
            float v3 = (facc[n][3] + bq.y) * qscale;
            split_pair(v0, v1, qa[0][n >> 1][(n & 1) * 2],     qa[1][n >> 1][(n & 1) * 2]);
            split_pair(v2, v3, qa[0][n >> 1][(n & 1) * 2 + 1], qa[1][n >> 1][(n & 1) * 2 + 1]);
        }

        // ---- S = Q K^T (16 x 128), 3 split terms ----
        float sacc[16][4];
#pragma unroll
        for (int n = 0; n < 16; n++)
#pragma unroll
            for (int e = 0; e < 4; e++) sacc[n][e] = 0.f;

#pragma unroll
        for (int n = 0; n < 16; n++) {
            int rr = n * 8 + (lane & 7);
            int off = SWZ(rr, lane >> 3);
            uint32_t kh[4], kl[4];
            ldsm4(kh, sK_hi + off);
            ldsm4(kl, sK_lo + off);
            mma16816(sacc[n], qa[0][0], kh[0], kh[1]);   // qh*kh  (d 0-15)
            mma16816(sacc[n], qa[0][1], kh[2], kh[3]);   //        (d 16-31)
            mma16816(sacc[n], qa[0][0], kl[0], kl[1]);   // qh*kl
            mma16816(sacc[n], qa[0][1], kl[2], kl[3]);
            mma16816(sacc[n], qa[1][0], kh[0], kh[1]);   // ql*kh
            mma16816(sacc[n], qa[1][1], kh[2], kh[3]);
        }

        // ---- bias + softmax ----
        const int qg1 = it * 128 + m0 + (lane >> 2);
        const int qg2 = qg1 + 8;
        const float* bp1 = g_bias + (size_t)h * 65536 + (size_t)qg1 * 128 + 2 * (lane & 3);
        const float* bp2 = g_bias + (size_t)h * 65536 + (size_t)qg2 * 128 + 2 * (lane & 3);
        float mx1 = -1e30f, mx2 = -1e30f;
#pragma unroll
        for (int n = 0; n < 16; n++) {
            float2 b1 = *(const float2*)(bp1 + 8 * n);
            float2 b2 = *(const float2*)(bp2 + 8 * n);
            sacc[n][0] += b1.x; sacc[n][1] += b1.y;
            sacc[n][2] += b2.x; sacc[n][3] += b2.y;
            mx1 = fmaxf(mx1, fmaxf(sacc[n][0], sacc[n][1]));
            mx2 = fmaxf(mx2, fmaxf(sacc[n][2], sacc[n][3]));
        }
        mx1 = fmaxf(mx1, __shfl_xor_sync(0xffffffffu, mx1, 1));
        mx1 = fmaxf(mx1, __shfl_xor_sync(0xffffffffu, mx1, 2));
        mx2 = fmaxf(mx2, __shfl_xor_sync(0xffffffffu, mx2, 1));
        mx2 = fmaxf(mx2, __shfl_xor_sync(0xffffffffu, mx2, 2));

        float sum1 = 0.f, sum2 = 0.f;
#pragma unroll
        for (int n = 0; n < 16; n++) {
            sacc[n][0] = __expf(sacc[n][0] - mx1); sum1 += sacc[n][0];
            sacc[n][1] = __expf(sacc[n][1] - mx1); sum1 += sacc[n][1];
            sacc[n][2] = __expf(sacc[n][2] - mx2); sum2 += sacc[n][2];
            sacc[n][3] = __expf(sacc[n][3] - mx2); sum2 += sacc[n][3];
        }
        sum1 += __shfl_xor_sync(0xffffffffu, sum1, 1);
        sum1 += __shfl_xor_sync(0xffffffffu, sum1, 2);
        sum2 += __shfl_xor_sync(0xffffffffu, sum2, 1);
        sum2 += __shfl_xor_sync(0xffffffffu, sum2, 2);
        const float inv1 = 1.0f / sum1;
        const float inv2 = 1.0f / sum2;

        // ---- O = P V (16 x 32), 3 split terms; lazy P-conversion per key chunk ----
        float oacc[4][4];
#pragma unroll
        for (int n = 0; n < 4; n++)
#pragma unroll
            for (int e = 0; e < 4; e++) oacc[n][e] = 0.f;

#pragma unroll
        for (int sh = 0; sh < 4; sh++) {        // key 32-chunks
            uint32_t pah0[4], pal0[4], pah1[4], pal1[4];
            split_pair(sacc[4*sh+0][0], sacc[4*sh+0][1], pah0[0], pal0[0]);
            split_pair(sacc[4*sh+0][2], sacc[4*sh+0][3], pah0[1], pal0[1]);
            split_pair(sacc[4*sh+1][0], sacc[4*sh+1][1], pah0[2], pal0[2]);
            split_pair(sacc[4*sh+1][2], sacc[4*sh+1][3], pah0[3], pal0[3]);
            split_pair(sacc[4*sh+2][0], sacc[4*sh+2][1], pah1[0], pal1[0]);
            split_pair(sacc[4*sh+2][2], sacc[4*sh+2][3], pah1[1], pal1[1]);
            split_pair(sacc[4*sh+3][0], sacc[4*sh+3][1], pah1[2], pal1[2]);
            split_pair(sacc[4*sh+3][2], sacc[4*sh+3][3], pah1[3], pal1[3]);

            int rr = sh * 32 + (lane >> 3) * 8 + (lane & 7);
#pragma unroll
            for (int n = 0; n < 4; n++) {       // d-groups of 8
                int off = SWZ(rr, n);
                uint32_t vh[4], vl[4];
                ldsm4t(vh, sV_hi + off);
                ldsm4t(vl, sV_lo + off);
                mma16816(oacc[n], pah0, vh[0], vh[1]);   // Ph*Vh
                mma16816(oacc[n], pah1, vh[2], vh[3]);
                mma16816(oacc[n], pal0, vh[0], vh[1]);   // Pl*Vh
                mma16816(oacc[n], pal1, vh[2], vh[3]);
                mma16816(oacc[n], pah0, vl[0], vl[1]);   // Ph*Vl
                mma16816(oacc[n], pah1, vl[2], vl[3]);
            }
        }

        // ---- store O (normalize by deferred 1/sum) ----
        float* o1 = outp + (size_t)(b * 512 + qg1) * 192 + h * 32 + 2 * (lane & 3);
        float* o2 = outp + (size_t)(b * 512 + qg2) * 192 + h * 32 + 2 * (lane & 3);
#pragma unroll
        for (int n = 0; n < 4; n++) {
            *(float2*)(o1 + 8 * n) = make_float2(oacc[n][0] * inv1, oacc[n][1] * inv1);
            *(float2*)(o2 + 8 * n) = make_float2(oacc[n][2] * inv2, oacc[n][3] * inv2);
        }
        // no __syncthreads needed: no smem writes inside the loop
    }
}

// ---------------- launch ----------------
extern "C" void kernel_launch(void* const* d_in, const int* in_sizes, int n_in,
                              void* d_out, int out_size)
{
    const float* kv         = (const float*)d_in[0];
    const float* q          = (const float*)d_in[1];
    const float* w_kv       = (const float*)d_in[2];
    const float* b_kv       = (const float*)d_in[3];
    const float* w_q        = (const float*)d_in[4];
    const float* b_q        = (const float*)d_in[5];
    const float* w_proj     = (const float*)d_in[6];
    const float* b_proj     = (const float*)d_in[7];
    const float* bias_table = (const float*)d_in[8];
    const int*   rel_index  = (const int*)  d_in[9];
    float* out = (float*)d_out;

    float *p_kvp, *p_att;
    cudaGetSymbolAddress((void**)&p_kvp, g_kvp);
    cudaGetSymbolAddress((void**)&p_att, g_att);

    bias_expand_kernel<<<1536, 256>>>(bias_table, rel_index);

    // kv projection: (32768 x 192) @ (192 x 384) + b_kv   (N = 4 x 96 exact)
    gemm_mma_kernel<<<dim3(4, 256), 256>>>(kv, w_kv, b_kv, p_kvp,
                                           32768, 192, 384, 1.0f);
    // fused q-projection + attention: one CTA per (batch, head)
    attn_mma_kernel<<<256 * 6, 256>>>(p_kvp, q, w_q, b_q, p_att);

    // output projection: (131072 x 192) @ (192 x 96) + b_proj   (N = 96 exact)
    gemm_mma_kernel<<<dim3(1, 1024), 256>>>(p_att, w_proj, b_proj, out,
                                            131072, 192, 96, 1.0f);
}

// round 17
// speedup vs baseline: 3.3611x; 1.0970x over previous
#include <cuda_runtime.h>
#include <cuda_bf16.h>
#include <cstdint>

// ---------------- problem constants ----------------
// kv:  (256, 128, 192)   q: (256, 512, 96)
// w_kv:(192,384) b_kv:(384)  w_q:(96,192) b_q:(192)
// w_proj:(192,96) b_proj:(96)
// bias_table:(3375,6)  rel_index:(512,128) int32
// out: (256, 512, 96) fp32

// ---------------- scratch (device globals, allowed) ----------------
__device__ float g_kvp[32768u * 384u];    // kv proj   [B*128, 384]
__device__ float g_att[131072u * 192u];   // attn out  [B*512, 192]
__device__ float g_bias[6u * 512u * 128u];// expanded bias [h][q][k]

// ---------------- warp-MMA helpers (baseline ISA: sm_80+) ----------------
__device__ __forceinline__ uint32_t smem_u32(const void* p) {
    uint32_t a;
    asm("{ .reg .u64 t; cvta.to.shared.u64 t, %1; cvt.u32.u64 %0, t; }"
        : "=r"(a) : "l"(p));
    return a;
}
__device__ __forceinline__ void ldsm4(uint32_t* r, uint32_t addr) {
    asm volatile("ldmatrix.sync.aligned.m8n8.x4.shared.b16 {%0,%1,%2,%3}, [%4];"
        : "=r"(r[0]), "=r"(r[1]), "=r"(r[2]), "=r"(r[3]) : "r"(addr));
}
__device__ __forceinline__ void ldsm4t(uint32_t* r, uint32_t addr) {
    asm volatile("ldmatrix.sync.aligned.m8n8.x4.trans.shared.b16 {%0,%1,%2,%3}, [%4];"
        : "=r"(r[0]), "=r"(r[1]), "=r"(r[2]), "=r"(r[3]) : "r"(addr));
}
// D(f32) += A(bf16) * B(bf16), m16n8k16, A row-major, B col-major
__device__ __forceinline__ void mma16816(float* c, const uint32_t* a,
                                         uint32_t b0, uint32_t b1) {
    asm volatile(
        "mma.sync.aligned.m16n8k16.row.col.f32.bf16.bf16.f32 "
        "{%0,%1,%2,%3}, {%4,%5,%6,%7}, {%8,%9}, {%0,%1,%2,%3};"
        : "+f"(c[0]), "+f"(c[1]), "+f"(c[2]), "+f"(c[3])
        : "r"(a[0]), "r"(a[1]), "r"(a[2]), "r"(a[3]), "r"(b0), "r"(b1));
}
// split (x,y) into bf16 hi pair (truncation) + bf16 lo pair (rn of remainder)
__device__ __forceinline__ void split_pair(float x, float y,
                                           uint32_t& hi, uint32_t& lo) {
    uint32_t bx = __float_as_uint(x);
    uint32_t by = __float_as_uint(y);
    uint32_t hpk;
    asm("prmt.b32 %0, %1, %2, 0x7632;" : "=r"(hpk) : "r"(bx), "r"(by));
    float lx = x - __uint_as_float(bx & 0xFFFF0000u);
    float ly = y - __uint_as_float(by & 0xFFFF0000u);
    uint32_t lpk;
    asm("cvt.rn.bf16x2.f32 %0, %1, %2;" : "=r"(lpk) : "f"(ly), "f"(lx));
    hi = hpk; lo = lpk;
}

// swizzled 16B-chunk offset inside a 64B-row tile (4 chunks/row)
#define SWZ(row, c)  (((row) << 6) + ((((c) ^ (((row) >> 1) & 3))) << 4))
// swizzled 16B-chunk offset inside a 192B-row tile (12 chunks/row).
// Bank-group of chunk = (12*row + (c ^ ((row>>1)&3))) mod 8 — distinct within
// every 8-row octet for any fixed c (see derivation in commit message).
#define WSWZ(row, c) ((row) * 192 + ((((c) ^ (((row) >> 1) & 3))) << 4))

// ---------------- bias expansion ----------------
__global__ __launch_bounds__(256) void bias_expand_kernel(
    const float* __restrict__ table, const int* __restrict__ rel)
{
    int idx = blockIdx.x * 256 + threadIdx.x;       // 6*512*128 = 393216
    if (idx >= 6 * 512 * 128) return;
    int h  = idx >> 16;
    int qk = idx & 65535;
    g_bias[idx] = table[rel[qk] * 6 + h];
}

// ================= split-bf16 HMMA GEMM, weights-resident =================
// C[M,N] = (A[M,K] @ W[K,N] + bias[N]) * scale, fp32 in/out.
// CTA tile 128M x 96N. W loaded to smem in 96-k phases (hi+lo bf16, 36.9 KB);
// A streamed from gmem straight into MMA fragments (no A smem, no per-chunk
// syncs — R14's fused-q-proj pattern). 3 syncs total for K=192.
// 3 split terms: Ah*Wh + Al*Wh + Ah*Wl.
// Requires: M % 128 == 0, K % 96 == 0 (and % 32), N % 96 == 0.
__global__ __launch_bounds__(256) void gemm_mma_kernel(
    const float* __restrict__ A, const float* __restrict__ W,
    const float* __restrict__ bias, float* __restrict__ C,
    int M, int K, int N, float scale)
{
    __shared__ __align__(16) char smem[36864];     // W hi 18432 | W lo 18432
    const uint32_t sW_hi = smem_u32(smem);
    const uint32_t sW_lo = sW_hi + 18432;

    const int tid  = threadIdx.x;
    const int w    = tid >> 5;
    const int lane = tid & 31;
    const int bm = blockIdx.y * 128;
    const int bn = blockIdx.x * 96;

    float acc[12][4];
#pragma unroll
    for (int n = 0; n < 12; n++)
#pragma unroll
        for (int e = 0; e < 4; e++) acc[n][e] = 0.f;

    const int m0 = w * 16;
    // A-fragment feed: row r1 = bm+m0+(lane>>2), r2 = r1+8; cols 2*(lane&3)+...
    const float* abase = A + (size_t)(bm + m0 + (lane >> 2)) * K + 2 * (lane & 3);

    for (int k0 = 0; k0 < K; k0 += 96) {
        if (k0) __syncthreads();                 // prior-phase reads complete
        // ---- load W phase: 96 k-rows x 96 n-cols, split bf16 ----
        for (int i = tid; i < 1152; i += 256) {  // 96 rows x 12 n-octets
            int kk = i / 12;
            int c  = i - kk * 12;
            const float* src = W + (size_t)(k0 + kk) * N + bn + 8 * c;
            float4 f0 = *(const float4*)(src);
            float4 f1 = *(const float4*)(src + 4);
            uint32_t hi[4], lo[4];
            split_pair(f0.x, f0.y, hi[0], lo[0]);
            split_pair(f0.z, f0.w, hi[1], lo[1]);
            split_pair(f1.x, f1.y, hi[2], lo[2]);
            split_pair(f1.z, f1.w, hi[3], lo[3]);
            int off = WSWZ(kk, c);
            *(uint4*)(smem + off)         = make_uint4(hi[0], hi[1], hi[2], hi[3]);
            *(uint4*)(smem + 18432 + off) = make_uint4(lo[0], lo[1], lo[2], lo[3]);
        }
        __syncthreads();

        // ---- 3 k-chunks of 32, sync-free ----
#pragma unroll
        for (int kc = 0; kc < 3; kc++) {
            uint32_t ah[2][4], al[2][4];
#pragma unroll
            for (int s = 0; s < 2; s++) {
                int kb = k0 + kc * 32 + 16 * s;
                float2 x0 = *(const float2*)(abase + kb);
                float2 x1 = *(const float2*)(abase + 8 * K + kb);
                float2 x2 = *(const float2*)(abase + kb + 8);
                float2 x3 = *(const float2*)(abase + 8 * K + kb + 8);
                split_pair(x0.x, x0.y, ah[s][0], al[s][0]);
                split_pair(x1.x, x1.y, ah[s][1], al[s][1]);
                split_pair(x2.x, x2.y, ah[s][2], al[s][2]);
                split_pair(x3.x, x3.y, ah[s][3], al[s][3]);
            }
            int rr = kc * 32 + (lane >> 3) * 8 + (lane & 7);   // phase-local k-row
#pragma unroll
            for (int no = 0; no < 12; no++) {
                int off = WSWZ(rr, no);
                uint32_t wh[4], wl[4];
                ldsm4t(wh, sW_hi + off);
                ldsm4t(wl, sW_lo + off);
                mma16816(acc[no], ah[0], wh[0], wh[1]);   // Ah*Wh  k 0-15
                mma16816(acc[no], ah[1], wh[2], wh[3]);   //        k 16-31
                mma16816(acc[no], al[0], wh[0], wh[1]);   // Al*Wh
                mma16816(acc[no], al[1], wh[2], wh[3]);
                mma16816(acc[no], ah[0], wl[0], wl[1]);   // Ah*Wl
                mma16816(acc[no], ah[1], wl[2], wl[3]);
            }
        }
    }

    // ---- epilogue: bias + scale (N exact multiple of 96, no masks) ----
    const int r1 = bm + m0 + (lane >> 2);
    const int r2 = r1 + 8;
    const int cb2 = 2 * (lane & 3);
#pragma unroll
    for (int no = 0; no < 12; no++) {
        int col = bn + 8 * no + cb2;
        float2 bv = *(const float2*)(bias + col);
        *(float2*)(C + (size_t)r1 * N + col) =
            make_float2((acc[no][0] + bv.x) * scale, (acc[no][1] + bv.y) * scale);
        *(float2*)(C + (size_t)r2 * N + col) =
            make_float2((acc[no][2] + bv.x) * scale, (acc[no][3] + bv.y) * scale);
    }
}

// ================= warp-MMA attention with fused q-projection =================
// One CTA per (b, h); 256 threads = 8 warps; 4 q-blocks of 128 rows, warp = 16-row strip.
// Q computed inline: facc = q(16x96) @ w_q_head(96x32) via 3-term HMMA (A-frags
// fed straight from gmem), then (facc + b_q)*qscale C-frags convert DIRECTLY
// into QK A-frags (C->A identity). No Q smem tiles, no per-iteration syncs.
// smem: Khi 8K | Klo 8K | Vhi 8K | Vlo 8K | WQhi 6K | WQlo 6K = 44 KB static.
__global__ __launch_bounds__(256, 2) void attn_mma_kernel(
    const float* __restrict__ kvp,    // [B*128, 384]
    const float* __restrict__ qraw,   // [B*512, 96]
    const float* __restrict__ w_q,    // [96, 192]
    const float* __restrict__ b_q,    // [192]
    float* __restrict__ outp)         // [B*512, 192]
{
    __shared__ __align__(16) char smem[45056];
    const uint32_t sK_hi = smem_u32(smem);
    const uint32_t sK_lo = sK_hi + 8192;
    const uint32_t sV_hi = sK_hi + 16384;
    const uint32_t sV_lo = sK_hi + 24576;
    const uint32_t sWQ_hi = sK_hi + 32768;
    const uint32_t sWQ_lo = sK_hi + 38912;

    const int tid  = threadIdx.x;
    const int w    = tid >> 5;
    const int lane = tid & 31;
    const int b = blockIdx.x / 6;
    const int h = blockIdx.x % 6;

    const float qscale = 0.17677669529663687f;  // 1/sqrt(32)

    // ---- prologue: K,V -> smem, split bf16 ----
    {
        const int r  = tid >> 1;
        const int hf = tid & 1;
        const float* src = kvp + (size_t)(b * 128 + r) * 384 + h * 32 + hf * 16;
        float kb[16], vb[16];
#pragma unroll
        for (int j = 0; j < 4; j++) {
            float4 f = *(const float4*)(src + 4 * j);
            kb[4*j] = f.x; kb[4*j+1] = f.y; kb[4*j+2] = f.z; kb[4*j+3] = f.w;
            float4 g = *(const float4*)(src + 192 + 4 * j);
            vb[4*j] = g.x; vb[4*j+1] = g.y; vb[4*j+2] = g.z; vb[4*j+3] = g.w;
        }
        uint32_t kh[8], kl[8], vh[8], vl[8];
#pragma unroll
        for (int p = 0; p < 8; p++) {
            split_pair(kb[2*p], kb[2*p+1], kh[p], kl[p]);
            split_pair(vb[2*p], vb[2*p+1], vh[p], vl[p]);
        }
#pragma unroll
        for (int j = 0; j < 2; j++) {
            int off = SWZ(r, hf * 2 + j);
            *(uint4*)(smem + 0     + off) = make_uint4(kh[4*j], kh[4*j+1], kh[4*j+2], kh[4*j+3]);
            *(uint4*)(smem + 8192  + off) = make_uint4(kl[4*j], kl[4*j+1], kl[4*j+2], kl[4*j+3]);
            *(uint4*)(smem + 16384 + off) = make_uint4(vh[4*j], vh[4*j+1], vh[4*j+2], vh[4*j+3]);
            *(uint4*)(smem + 24576 + off) = make_uint4(vl[4*j], vl[4*j+1], vl[4*j+2], vl[4*j+3]);
        }
    }
    // ---- prologue: w_q head slice (96 x 32) -> smem, split bf16 ----
    if (tid < 192) {
        const int r  = tid >> 1;      // k-row 0..95
        const int hf = tid & 1;       // 16-col half
        const float* src = w_q + (size_t)r * 192 + h * 32 + hf * 16;
        float wv[16];
#pragma unroll
        for (int j = 0; j < 4; j++) {
            float4 f = *(const float4*)(src + 4 * j);
            wv[4*j] = f.x; wv[4*j+1] = f.y; wv[4*j+2] = f.z; wv[4*j+3] = f.w;
        }
        uint32_t hi[8], lo[8];
#pragma unroll
        for (int p = 0; p < 8; p++)
            split_pair(wv[2*p], wv[2*p+1], hi[p], lo[p]);
#pragma unroll
        for (int j = 0; j < 2; j++) {
            int off = SWZ(r, hf * 2 + j);
            *(uint4*)(smem + 32768 + off) = make_uint4(hi[4*j], hi[4*j+1], hi[4*j+2], hi[4*j+3]);
            *(uint4*)(smem + 38912 + off) = make_uint4(lo[4*j], lo[4*j+1], lo[4*j+2], lo[4*j+3]);
        }
    }
    __syncthreads();   // only block-wide sync: all smem is read-only after this

    const int m0 = w * 16;

    for (int it = 0; it < 4; it++) {
        // ---- fused q-projection: facc(16x32) = q(16x96) @ w_q_head, 3 terms ----
        float facc[4][4];
#pragma unroll
        for (int n = 0; n < 4; n++)
#pragma unroll
            for (int e = 0; e < 4; e++) facc[n][e] = 0.f;

        const float* qbase = qraw
            + (size_t)(b * 512 + it * 128 + m0 + (lane >> 2)) * 96 + 2 * (lane & 3);
#pragma unroll
        for (int kq = 0; kq < 3; kq++) {
            uint32_t ah[2][4], al[2][4];
#pragma unroll
            for (int s = 0; s < 2; s++) {
                int kb = 32 * kq + 16 * s;
                float2 x0 = *(const float2*)(qbase + kb);
                float2 x1 = *(const float2*)(qbase + 8 * 96 + kb);
                float2 x2 = *(const float2*)(qbase + kb + 8);
                float2 x3 = *(const float2*)(qbase + 8 * 96 + kb + 8);
                split_pair(x0.x, x0.y, ah[s][0], al[s][0]);
                split_pair(x1.x, x1.y, ah[s][1], al[s][1]);
                split_pair(x2.x, x2.y, ah[s][2], al[s][2]);
                split_pair(x3.x, x3.y, ah[s][3], al[s][3]);
            }
            int rr = kq * 32 + (lane >> 3) * 8 + (lane & 7);
#pragma unroll
            for (int no = 0; no < 4; no++) {
                int off = SWZ(rr, no);
                uint32_t wh[4], wl[4];
                ldsm4t(wh, sWQ_hi + off);
                ldsm4t(wl, sWQ_lo + off);
                mma16816(facc[no], ah[0], wh[0], wh[1]);   // Ah*Wh
                mma16816(facc[no], ah[1], wh[2], wh[3]);
                mma16816(facc[no], al[0], wh[0], wh[1]);   // Al*Wh
                mma16816(facc[no], al[1], wh[2], wh[3]);
                mma16816(facc[no], ah[0], wl[0], wl[1]);   // Ah*Wl
                mma16816(facc[no], ah[1], wl[2], wl[3]);
            }
        }

        // ---- (facc + b_q) * qscale  ->  QK A-frags (C->A layout identity) ----
        uint32_t qa[2][2][4];
#pragma unroll
        for (int n = 0; n < 4; n++) {
            float2 bq = *(const float2*)(b_q + h * 32 + 8 * n + 2 * (lane & 3));
            float v0 = (facc[n][0] + bq.x) * qscale;
            float v1 = (facc[n][1] + bq.y) * qscale;
            float v2 = (facc[n][2] + bq.x) * qscale;
            float v3 = (facc[n][3] + bq.y) * qscale;
            split_pair(v0, v1, qa[0][n >> 1][(n & 1) * 2],     qa[1][n >> 1][(n & 1) * 2]);
            split_pair(v2, v3, qa[0][n >> 1][(n & 1) * 2 + 1], qa[1][n >> 1][(n & 1) * 2 + 1]);
        }

        // ---- S = Q K^T (16 x 128), 3 split terms ----
        float sacc[16][4];
#pragma unroll
        for (int n = 0; n < 16; n++)
#pragma unroll
            for (int e = 0; e < 4; e++) sacc[n][e] = 0.f;

#pragma unroll
        for (int n = 0; n < 16; n++) {
            int rr = n * 8 + (lane & 7);
            int off = SWZ(rr, lane >> 3);
            uint32_t kh[4], kl[4];
            ldsm4(kh, sK_hi + off);
            ldsm4(kl, sK_lo + off);
            mma16816(sacc[n], qa[0][0], kh[0], kh[1]);   // qh*kh  (d 0-15)
            mma16816(sacc[n], qa[0][1], kh[2], kh[3]);   //        (d 16-31)
            mma16816(sacc[n], qa[0][0], kl[0], kl[1]);   // qh*kl
            mma16816(sacc[n], qa[0][1], kl[2], kl[3]);
            mma16816(sacc[n], qa[1][0], kh[0], kh[1]);   // ql*kh
            mma16816(sacc[n], qa[1][1], kh[2], kh[3]);
        }

        // ---- bias + softmax ----
        const int qg1 = it * 128 + m0 + (lane >> 2);
        const int qg2 = qg1 + 8;
        const float* bp1 = g_bias + (size_t)h * 65536 + (size_t)qg1 * 128 + 2 * (lane & 3);
        const float* bp2 = g_bias + (size_t)h * 65536 + (size_t)qg2 * 128 + 2 * (lane & 3);
        float mx1 = -1e30f, mx2 = -1e30f;
#pragma unroll
        for (int n = 0; n < 16; n++) {
            float2 b1 = *(const float2*)(bp1 + 8 * n);
            float2 b2 = *(const float2*)(bp2 + 8 * n);
            sacc[n][0] += b1.x; sacc[n][1] += b1.y;
            sacc[n][2] += b2.x; sacc[n][3] += b2.y;
            mx1 = fmaxf(mx1, fmaxf(sacc[n][0], sacc[n][1]));
            mx2 = fmaxf(mx2, fmaxf(sacc[n][2], sacc[n][3]));
        }
        mx1 = fmaxf(mx1, __shfl_xor_sync(0xffffffffu, mx1, 1));
        mx1 = fmaxf(mx1, __shfl_xor_sync(0xffffffffu, mx1, 2));
        mx2 = fmaxf(mx2, __shfl_xor_sync(0xffffffffu, mx2, 1));
        mx2 = fmaxf(mx2, __shfl_xor_sync(0xffffffffu, mx2, 2));

        float sum1 = 0.f, sum2 = 0.f;
#pragma unroll
        for (int n = 0; n < 16; n++) {
            sacc[n][0] = __expf(sacc[n][0] - mx1); sum1 += sacc[n][0];
            sacc[n][1] = __expf(sacc[n][1] - mx1); sum1 += sacc[n][1];
            sacc[n][2] = __expf(sacc[n][2] - mx2); sum2 += sacc[n][2];
            sacc[n][3] = __expf(sacc[n][3] - mx2); sum2 += sacc[n][3];
        }
        sum1 += __shfl_xor_sync(0xffffffffu, sum1, 1);
        sum1 += __shfl_xor_sync(0xffffffffu, sum1, 2);
        sum2 += __shfl_xor_sync(0xffffffffu, sum2, 1);
        sum2 += __shfl_xor_sync(0xffffffffu, sum2, 2);
        const float inv1 = 1.0f / sum1;
        const float inv2 = 1.0f / sum2;

        // ---- O = P V (16 x 32), 3 split terms; lazy P-conversion per key chunk ----
        float oacc[4][4];
#pragma unroll
        for (int n = 0; n < 4; n++)
#pragma unroll
            for (int e = 0; e < 4; e++) oacc[n][e] = 0.f;

#pragma unroll
        for (int sh = 0; sh < 4; sh++) {        // key 32-chunks
            uint32_t pah0[4], pal0[4], pah1[4], pal1[4];
            split_pair(sacc[4*sh+0][0], sacc[4*sh+0][1], pah0[0], pal0[0]);
            split_pair(sacc[4*sh+0][2], sacc[4*sh+0][3], pah0[1], pal0[1]);
            split_pair(sacc[4*sh+1][0], sacc[4*sh+1][1], pah0[2], pal0[2]);
            split_pair(sacc[4*sh+1][2], sacc[4*sh+1][3], pah0[3], pal0[3]);
            split_pair(sacc[4*sh+2][0], sacc[4*sh+2][1], pah1[0], pal1[0]);
            split_pair(sacc[4*sh+2][2], sacc[4*sh+2][3], pah1[1], pal1[1]);
            split_pair(sacc[4*sh+3][0], sacc[4*sh+3][1], pah1[2], pal1[2]);
            split_pair(sacc[4*sh+3][2], sacc[4*sh+3][3], pah1[3], pal1[3]);

            int rr = sh * 32 + (lane >> 3) * 8 + (lane & 7);
#pragma unroll
            for (int n = 0; n < 4; n++) {       // d-groups of 8
                int off = SWZ(rr, n);
                uint32_t vh[4], vl[4];
                ldsm4t(vh, sV_hi + off);
                ldsm4t(vl, sV_lo + off);
                mma16816(oacc[n], pah0, vh[0], vh[1]);   // Ph*Vh
                mma16816(oacc[n], pah1, vh[2], vh[3]);
                mma16816(oacc[n], pal0, vh[0], vh[1]);   // Pl*Vh
                mma16816(oacc[n], pal1, vh[2], vh[3]);
                mma16816(oacc[n], pah0, vl[0], vl[1]);   // Ph*Vl
                mma16816(oacc[n], pah1, vl[2], vl[3]);
            }
        }

        // ---- store O (normalize by deferred 1/sum) ----
        float* o1 = outp + (size_t)(b * 512 + qg1) * 192 + h * 32 + 2 * (lane & 3);
        float* o2 = outp + (size_t)(b * 512 + qg2) * 192 + h * 32 + 2 * (lane & 3);
#pragma unroll
        for (int n = 0; n < 4; n++) {
            *(float2*)(o1 + 8 * n) = make_float2(oacc[n][0] * inv1, oacc[n][1] * inv1);
            *(float2*)(o2 + 8 * n) = make_float2(oacc[n][2] * inv2, oacc[n][3] * inv2);
        }
        // no __syncthreads needed: no smem writes inside the loop
    }
}

// ---------------- launch ----------------
extern "C" void kernel_launch(void* const* d_in, const int* in_sizes, int n_in,
                              void* d_out, int out_size)
{
    const float* kv         = (const float*)d_in[0];
    const float* q          = (const float*)d_in[1];
    const float* w_kv       = (const float*)d_in[2];
    const float* b_kv       = (const float*)d_in[3];
    const float* w_q        = (const float*)d_in[4];
    const float* b_q        = (const float*)d_in[5];
    const float* w_proj     = (const float*)d_in[6];
    const float* b_proj     = (const float*)d_in[7];
    const float* bias_table = (const float*)d_in[8];
    const int*   rel_index  = (const int*)  d_in[9];
    float* out = (float*)d_out;

    float *p_kvp, *p_att;
    cudaGetSymbolAddress((void**)&p_kvp, g_kvp);
    cudaGetSymbolAddress((void**)&p_att, g_att);

    bias_expand_kernel<<<1536, 256>>>(bias_table, rel_index);

    // kv projection: (32768 x 192) @ (192 x 384) + b_kv   (N = 4 x 96 exact)
    gemm_mma_kernel<<<dim3(4, 256), 256>>>(kv, w_kv, b_kv, p_kvp,
                                           32768, 192, 384, 1.0f);
    // fused q-projection + attention: one CTA per (batch, head)
    attn_mma_kernel<<<256 * 6, 256>>>(p_kvp, q, w_q, b_q, p_att);

    // output projection: (131072 x 192) @ (192 x 96) + b_proj   (N = 96 exact)
    gemm_mma_kernel<<<dim3(1, 1024), 256>>>(p_att, w_proj, b_proj, out,
                                            131072, 192, 96, 1.0f);
}